// round 11
// baseline (speedup 1.0000x reference)
#include <cuda_runtime.h>
#include <cuda_bf16.h>
#include <cstdint>
#include <math.h>

#define TT 256
#define BB 32
#define HH 256
#define KK 48
#define GATES 1024          // 4*H
#define ROWS_TB (TT*BB)     // 8192

// ---------------- device scratch (no allocations allowed) ----------------
__device__ float g_x0[ROWS_TB * 256];        // embedded input (t,b,e)
__device__ float g_gxf[ROWS_TB * GATES];     // x@Wih^T + b, fwd
__device__ float g_gxb[ROWS_TB * GATES];     // x@Wih^T + b, bwd
__device__ float g_h1[ROWS_TB * 512];        // layer-0 output (hf|hb)
__device__ float g_h2[ROWS_TB * 512];        // layer-1 output
__device__ float g_emit[ROWS_TB * KK];       // emissions (t,b,k)
__device__ float g_scr[BB];                  // per-batch (num-den)

// L2-exchange: h[par][dir][bg8][4*256] fp32, flags [dir][bg8][rank8]
__device__ float g_hx[2 * 2 * 8 * 1024];     // 128 KB
__device__ int   g_flag[2 * 8 * 8];          // 128 ints

// output layout: [emit (B,T,K) fp32 | loss | mask (B,T)]
#define EMIT_N   (BB*TT*KK)      // 393216
#define LOSS_OFF EMIT_N
#define MASK_OFF (EMIT_N + 1)

// ---------------- helpers ----------------
__device__ __forceinline__ float sigf(float x) { return 1.0f / (1.0f + __expf(-x)); }

__device__ __forceinline__ uint32_t smem_u32(const void* p) {
    uint32_t a;
    asm("{ .reg .u64 t; cvta.to.shared.u64 t, %1; cvt.u32.u64 %0, t; }" : "=r"(a) : "l"(p));
    return a;
}
// pack (lo half = a, hi half = b) into bf16x2
__device__ __forceinline__ uint32_t pk2(float a, float b) {
    uint32_t r;
    asm("cvt.rn.bf16x2.f32 %0, %1, %2;" : "=r"(r) : "f"(b), "f"(a));
    return r;
}
__device__ __forceinline__ void ldm_x4(uint32_t* r, uint32_t addr) {
    asm volatile("ldmatrix.sync.aligned.m8n8.x4.shared.b16 {%0,%1,%2,%3}, [%4];"
                 : "=r"(r[0]), "=r"(r[1]), "=r"(r[2]), "=r"(r[3]) : "r"(addr));
}
__device__ __forceinline__ void ldm_x2(uint32_t* r, uint32_t addr) {
    asm volatile("ldmatrix.sync.aligned.m8n8.x2.shared.b16 {%0,%1}, [%2];"
                 : "=r"(r[0]), "=r"(r[1]) : "r"(addr));
}
__device__ __forceinline__ void mma16816(float* c, const uint32_t* a, const uint32_t* b) {
    asm volatile("mma.sync.aligned.m16n8k16.row.col.f32.bf16.bf16.f32 "
                 "{%0,%1,%2,%3}, {%4,%5,%6,%7}, {%8,%9}, {%0,%1,%2,%3};"
                 : "+f"(c[0]), "+f"(c[1]), "+f"(c[2]), "+f"(c[3])
                 : "r"(a[0]), "r"(a[1]), "r"(a[2]), "r"(a[3]), "r"(b[0]), "r"(b[1]));
}
__device__ __forceinline__ int ld_acq(const int* p) {
    int v;
    asm volatile("ld.acquire.gpu.global.s32 %0, [%1];" : "=r"(v) : "l"(p) : "memory");
    return v;
}
__device__ __forceinline__ void st_rel(int* p, int v) {
    asm volatile("st.relaxed.gpu.global.s32 [%0], %1;" :: "l"(p), "r"(v) : "memory");
}

// ---------------- embedding gather ----------------
__global__ void embed_kernel(const int* __restrict__ sent,
                             const float* __restrict__ embed,
                             float* __restrict__ x0) {
    int bid = blockIdx.x;            // t*32 + b
    int t = bid >> 5, b = bid & 31;
    int tok = sent[b * TT + t];
    x0[(size_t)bid * 256 + threadIdx.x] = embed[(size_t)tok * 256 + threadIdx.x];
}

// ---------------- mma.sync bf16x3 GEMM: C[M,N] = A[M,K] * W[N,K]^T + bias ----------------
#define MG_AHI 0
#define MG_ALO 18432
#define MG_BHI 36864
#define MG_BLO 46080
#define MG_TOTAL 55296
#define APITCH 72

__global__ void __launch_bounds__(256)
mma_gemm(const float* __restrict__ A,
         const float* __restrict__ Wf, const float* __restrict__ Wb,
         const float* __restrict__ biasf, const float* __restrict__ biasb,
         float* __restrict__ Cf, float* __restrict__ Cb,
         int K, int Nout) {
    extern __shared__ char smc[];
    uint32_t sb = smem_u32(smc);
    int tid = threadIdx.x, wid = tid >> 5, l = tid & 31;
    int m0 = blockIdx.y * 128, n0 = blockIdx.x * 64;
    const float* W    = blockIdx.z ? Wb : Wf;
    const float* bias = blockIdx.z ? biasb : biasf;
    float*       C    = blockIdx.z ? Cb : Cf;

    int wm = wid & 3, wn = wid >> 2;
    int srow = tid >> 4;
    int scol = (tid & 15) << 2;

    float c[2][4][4];
#pragma unroll
    for (int mi = 0; mi < 2; mi++)
#pragma unroll
        for (int ni = 0; ni < 4; ni++)
#pragma unroll
            for (int j = 0; j < 4; j++) c[mi][ni][j] = 0.0f;

    int nch = K >> 6;
    for (int ch = 0; ch < nch; ch++) {
        int kc = ch << 6;
#pragma unroll
        for (int rr = 0; rr < 8; rr++) {
            int row = srow + rr * 16;
            float4 v = *(const float4*)&A[(size_t)(m0 + row) * K + kc + scol];
            float hx = __bfloat162float(__float2bfloat16(v.x));
            float hy = __bfloat162float(__float2bfloat16(v.y));
            float hz = __bfloat162float(__float2bfloat16(v.z));
            float hw = __bfloat162float(__float2bfloat16(v.w));
            uint32_t off = (uint32_t)(row * APITCH + scol) * 2;
            *(uint2*)(smc + MG_AHI + off) = make_uint2(pk2(hx, hy), pk2(hz, hw));
            *(uint2*)(smc + MG_ALO + off) =
                make_uint2(pk2(v.x - hx, v.y - hy), pk2(v.z - hz, v.w - hw));
        }
#pragma unroll
        for (int rr = 0; rr < 4; rr++) {
            int row = srow + rr * 16;
            int n = n0 + row;
            float4 v = make_float4(0.f, 0.f, 0.f, 0.f);
            if (n < Nout) v = *(const float4*)&W[(size_t)n * K + kc + scol];
            float hx = __bfloat162float(__float2bfloat16(v.x));
            float hy = __bfloat162float(__float2bfloat16(v.y));
            float hz = __bfloat162float(__float2bfloat16(v.z));
            float hw = __bfloat162float(__float2bfloat16(v.w));
            uint32_t off = (uint32_t)(row * APITCH + scol) * 2;
            *(uint2*)(smc + MG_BHI + off) = make_uint2(pk2(hx, hy), pk2(hz, hw));
            *(uint2*)(smc + MG_BLO + off) =
                make_uint2(pk2(v.x - hx, v.y - hy), pk2(v.z - hz, v.w - hw));
        }
        __syncthreads();

#pragma unroll
        for (int ks = 0; ks < 4; ks++) {
            uint32_t ah[2][4], al[2][4];
#pragma unroll
            for (int mi = 0; mi < 2; mi++) {
                uint32_t off =
                    (uint32_t)((wm * 32 + mi * 16 + (l & 15)) * APITCH +
                               ks * 16 + (l >> 4) * 8) * 2;
                ldm_x4(ah[mi], sb + MG_AHI + off);
                ldm_x4(al[mi], sb + MG_ALO + off);
            }
            uint32_t bh[4][2], bl[4][2];
#pragma unroll
            for (int ni = 0; ni < 4; ni++) {
                uint32_t off =
                    (uint32_t)((wn * 32 + ni * 8 + (l & 7)) * APITCH +
                               ks * 16 + ((l >> 3) & 1) * 8) * 2;
                ldm_x2(bh[ni], sb + MG_BHI + off);
                ldm_x2(bl[ni], sb + MG_BLO + off);
            }
#pragma unroll
            for (int mi = 0; mi < 2; mi++)
#pragma unroll
                for (int ni = 0; ni < 4; ni++) {
                    mma16816(c[mi][ni], ah[mi], bh[ni]);
                    mma16816(c[mi][ni], al[mi], bh[ni]);
                    mma16816(c[mi][ni], ah[mi], bl[ni]);
                }
        }
        __syncthreads();
    }

#pragma unroll
    for (int mi = 0; mi < 2; mi++) {
#pragma unroll
        for (int ni = 0; ni < 4; ni++) {
#pragma unroll
            for (int j = 0; j < 4; j++) {
                int row = m0 + wm * 32 + mi * 16 + (l >> 2) + (j >> 1) * 8;
                int col = n0 + wn * 32 + ni * 8 + (l & 3) * 2 + (j & 1);
                if (col < Nout)
                    C[(size_t)row * Nout + col] = c[mi][ni][j] + bias[col];
            }
        }
    }
}

// ---------------- reset for the L2-exchange state ----------------
__global__ void lstm_reset() {
    int idx = blockIdx.x * blockDim.x + threadIdx.x;
    if (idx < 2 * 2 * 8 * 1024) g_hx[idx] = 0.0f;
    if (idx < 2 * 8 * 8) g_flag[idx] = 0;
}

// ---------------- BiLSTM layer v7: HMMA compute + L2 flag exchange ----------------
// v5b partition (8 ranks x 8 bg(4 batches) x 2 dir = 128 CTAs) and sync protocol,
// v3 HMMA matvec (W bf16 hi/lo in SMEM, pitch 264; h bf16 hi/lo B-operand).
// h is exchanged fp32 through L2; the consumer converts 4 floats/thread into
// the ldmatrix layout (2x STS.64). Pad batch-rows 4-7 zeroed once at init.
#define WP2 264
#define L_WHI 0                          // 128*264*2 = 67584 B
#define L_WLO 67584
#define L_HBHI 135168                    // 8 rows * 264 bf16 * 2 = 4224 B
#define L_HBLO 139392
#define L_GSM 143616                     // 128*5 floats = 2560 B
#define L_TOTAL 146176

__global__ void __launch_bounds__(256, 1)
lstm_layer(const float* __restrict__ GxF, const float* __restrict__ GxB,
           const float* __restrict__ WhhF, const float* __restrict__ WhhB,
           const int* __restrict__ lengths, float* __restrict__ Hout) {
    extern __shared__ char smc[];
    uint32_t sb = smem_u32(smc);
    float* gsmf = (float*)(smc + L_GSM);

    int tid = threadIdx.x;
    int wid = tid >> 5, l = tid & 31;
    int r   = blockIdx.x & 7;
    int cid = blockIdx.x >> 3;
    int dir = cid >> 3;
    int bg  = cid & 7;
    int batch0 = bg * 4;

    const float* Gx  = dir ? GxB : GxF;
    const float* Whh = dir ? WhhB : WhhF;

    int* flg_base = g_flag + (dir * 8 + bg) * 8;

    // stage Whh slice split into bf16 hi/lo: W[g][k], pitch 264 bf16
    for (int idx = tid; idx < 128 * 64; idx += 256) {
        int g = idx >> 6;
        int kq = (idx & 63) << 2;
        int grow = ((g >> 5) << 8) + (r << 5) + (g & 31);
        float4 v = *(const float4*)&Whh[(size_t)grow * 256 + kq];
        float hx = __bfloat162float(__float2bfloat16(v.x));
        float hy = __bfloat162float(__float2bfloat16(v.y));
        float hz = __bfloat162float(__float2bfloat16(v.z));
        float hw = __bfloat162float(__float2bfloat16(v.w));
        uint32_t off = (uint32_t)(g * WP2 + kq) * 2;
        *(uint2*)(smc + L_WHI + off) = make_uint2(pk2(hx, hy), pk2(hz, hw));
        *(uint2*)(smc + L_WLO + off) =
            make_uint2(pk2(v.x - hx, v.y - hy), pk2(v.z - hz, v.w - hw));
    }
    // zero h B-operand buffers (all 8 rows incl. pad, hi+lo)
    for (int i = tid; i < (4224 * 2) / 4; i += 256)
        *(uint32_t*)(smc + L_HBHI + i * 4) = 0;
    __syncthreads();

    // per-thread invariant MMA addresses (from validated v3 kernel)
    uint32_t aoff_hi = sb + L_WHI + (uint32_t)((16 * wid + (l & 15)) * WP2 + (l >> 4) * 8) * 2;
    uint32_t aoff_lo = aoff_hi + (uint32_t)(L_WLO - L_WHI);
    uint32_t boff_hi = sb + L_HBHI + (uint32_t)(((l & 7) * WP2 + ((l >> 3) & 1) * 8)) * 2;
    uint32_t boff_lo = boff_hi + (uint32_t)(L_HBLO - L_HBHI);

    // conversion mapping: thread -> (batch row, 4 k values)
    int cvb = tid >> 6;                  // 0..3
    int cvk = (tid & 63) << 2;           // 0..252

    int b2 = tid >> 5, uu = tid & 31;    // producer mapping (tid<128)
    int mylen = 0;
    if (tid < 128) mylen = lengths[batch0 + b2];
    float creg = 0.0f, hreg = 0.0f;

    for (int s = 0; s < TT; ++s) {
        int t = dir ? (TT - 1 - s) : s;
        int par = s & 1;
        bool last = (s == TT - 1);

        // prefetch gate-x for this step (producers) before polling
        float gxi = 0.f, gxfv = 0.f, gxg = 0.f, gxo = 0.f;
        if (tid < 128) {
            const float* gp = Gx + ((size_t)t * BB + batch0 + b2) * GATES + (r << 5) + uu;
            gxi = gp[0]; gxfv = gp[256]; gxg = gp[512]; gxo = gp[768];
        }

        // wait for all 8 ranks' h slices for this step
        if (s > 0) {
            for (;;) {
                bool ok = (l < 8) ? (ld_acq(flg_base + l) >= s) : true;
                if (__all_sync(0xffffffffu, ok)) break;
            }
        }

        // copy+convert h: fp32 (L2) -> bf16 hi/lo in ldmatrix layout
        {
            const float4* src = (const float4*)(g_hx + ((par * 2 + dir) * 8 + bg) * 1024);
            float4 v = __ldcg(src + tid);        // tid -> batch cvb, k cvk..cvk+3
            float hx = __bfloat162float(__float2bfloat16(v.x));
            float hy = __bfloat162float(__float2bfloat16(v.y));
            float hz = __bfloat162float(__float2bfloat16(v.z));
            float hw = __bfloat162float(__float2bfloat16(v.w));
            uint32_t off = (uint32_t)(cvb * WP2 + cvk) * 2;
            *(uint2*)(smc + L_HBHI + off) = make_uint2(pk2(hx, hy), pk2(hz, hw));
            *(uint2*)(smc + L_HBLO + off) =
                make_uint2(pk2(v.x - hx, v.y - hy), pk2(v.z - hz, v.w - hw));
        }
        __syncthreads();

        // HMMA matvec: warp wid owns gates 16*wid..16*wid+15, all 256 k
        float chh[4] = {0, 0, 0, 0}, clh[4] = {0, 0, 0, 0}, chl[4] = {0, 0, 0, 0};
#pragma unroll
        for (int kt = 0; kt < 16; kt++) {
            uint32_t whi[4], wlo[4], bhi[2], blo[2];
            ldm_x4(whi, aoff_hi + kt * 32);
            ldm_x4(wlo, aoff_lo + kt * 32);
            ldm_x2(bhi, boff_hi + kt * 32);
            ldm_x2(blo, boff_lo + kt * 32);
            mma16816(chh, whi, bhi);
            mma16816(clh, wlo, bhi);
            mma16816(chl, whi, blo);
        }

        if ((l & 3) < 2) {
            int colb = (l & 3) * 2;
            int rb = 16 * wid + (l >> 2);
            gsmf[rb * 5 + colb]           = chh[0] + clh[0] + chl[0];
            gsmf[rb * 5 + colb + 1]       = chh[1] + clh[1] + chl[1];
            gsmf[(rb + 8) * 5 + colb]     = chh[2] + clh[2] + chl[2];
            gsmf[(rb + 8) * 5 + colb + 1] = chh[3] + clh[3] + chl[3];
        }
        __syncthreads();

        if (tid < 128) {
            float iv = gsmf[uu * 5 + b2]        + gxi;
            float fv = gsmf[(32 + uu) * 5 + b2] + gxfv;
            float gv = gsmf[(64 + uu) * 5 + b2] + gxg;
            float ov = gsmf[(96 + uu) * 5 + b2] + gxo;
            float c2 = sigf(fv) * creg + sigf(iv) * tanhf(gv);
            float h2 = sigf(ov) * tanhf(c2);
            bool m = (t < mylen);
            float hn = m ? h2 : hreg;
            creg = m ? c2 : creg;
            hreg = hn;

            if (!last) {
                // publish own slice for step s+1 into parity par^1 (fp32)
                g_hx[(((par ^ 1) * 2 + dir) * 8 + bg) * 1024 +
                     (b2 << 8) + (r << 5) + uu] = hn;
            }
            Hout[((size_t)t * BB + batch0 + b2) * 512 + dir * 256 + (r << 5) + uu] =
                m ? h2 : 0.0f;
        }
        __syncthreads();                 // all producer stores done (CTA-level HB)
        if (!last && tid == 0) { __threadfence(); st_rel(flg_base + r, s + 1); }
    }
}

// ---------------- emit transpose + mask output ----------------
__global__ void finalize_kernel(const float* __restrict__ emitb,
                                const int* __restrict__ sent,
                                float* __restrict__ out, int out_size) {
    int bid = blockIdx.x;            // b*256 + t
    int b = bid >> 8, t = bid & 255;
    int k = threadIdx.x;
    if (k < KK) out[(size_t)bid * KK + k] = emitb[((size_t)t * BB + b) * KK + k];
    if (k == KK) {
        int idx = MASK_OFF + bid;
        if (idx < out_size) out[idx] = (sent[bid] != 0) ? 1.0f : 0.0f;
    }
}

// ---------------- CRF ----------------
__global__ void crf_kernel(const float* __restrict__ emitb,
                           const int* __restrict__ tags,
                           const int* __restrict__ lengths,
                           const float* __restrict__ start_t,
                           const float* __restrict__ end_t,
                           const float* __restrict__ trans,
                           float* __restrict__ scratch) {
    int b = blockIdx.x;
    int tid = threadIdx.x;           // 64
    __shared__ float trs[KK * KK];
    __shared__ float score[KK];
    __shared__ float nsc[KK];
    __shared__ float rbuf[64];
    __shared__ float numsh;

    for (int i = tid; i < KK * KK; i += 64) trs[i] = trans[i];
    int len = lengths[b];
    __syncthreads();

    float part = 0.0f;
    for (int t = 1 + tid; t < len; t += 64) {
        int tg = tags[b * TT + t];
        int pg = tags[b * TT + t - 1];
        part += trs[pg * KK + tg] + emitb[((size_t)t * BB + b) * KK + tg];
    }
    rbuf[tid] = part;
    __syncthreads();
    for (int s = 32; s > 0; s >>= 1) {
        if (tid < s) rbuf[tid] += rbuf[tid + s];
        __syncthreads();
    }
    if (tid == 0) {
        int t0 = tags[b * TT + 0];
        numsh = rbuf[0] + start_t[t0] + emitb[(size_t)b * KK + t0]
              + end_t[tags[b * TT + len - 1]];
    }

    if (tid < KK) score[tid] = start_t[tid] + emitb[(size_t)b * KK + tid];
    __syncthreads();
    for (int t = 1; t < len; t++) {
        if (tid < KK) {
            int k = tid;
            float m = -1e30f;
#pragma unroll 4
            for (int j = 0; j < KK; j++) {
                float v = score[j] + trs[j * KK + k];
                m = fmaxf(m, v);
            }
            float ssum = 0.0f;
#pragma unroll 4
            for (int j = 0; j < KK; j++)
                ssum += expf(score[j] + trs[j * KK + k] - m);
            nsc[k] = m + logf(ssum) + emitb[((size_t)t * BB + b) * KK + k];
        }
        __syncthreads();
        if (tid < KK) score[tid] = nsc[tid];
        __syncthreads();
    }
    if (tid == 0) {
        float m = -1e30f;
        for (int k = 0; k < KK; k++) m = fmaxf(m, score[k] + end_t[k]);
        float ssum = 0.0f;
        for (int k = 0; k < KK; k++) ssum += expf(score[k] + end_t[k] - m);
        float den = m + logf(ssum);
        scratch[b] = numsh - den;
    }
}

__global__ void loss_kernel(const float* __restrict__ scratch,
                            float* __restrict__ out, int out_size) {
    if (threadIdx.x == 0 && LOSS_OFF < out_size) {
        float s = 0.0f;
        for (int b = 0; b < BB; b++) s += scratch[b];
        out[LOSS_OFF] = s / (float)BB;
    }
}

// ---------------- launch ----------------
extern "C" void kernel_launch(void* const* d_in, const int* in_sizes, int n_in,
                              void* d_out, int out_size) {
    const int*   sentence = (const int*)d_in[0];
    const int*   lengths  = (const int*)d_in[1];
    const int*   tags     = (const int*)d_in[2];
    const float* embed    = (const float*)d_in[3];
    const float* Wih0f = (const float*)d_in[4];
    const float* Whh0f = (const float*)d_in[5];
    const float* b0f   = (const float*)d_in[6];
    const float* Wih0b = (const float*)d_in[7];
    const float* Whh0b = (const float*)d_in[8];
    const float* b0b   = (const float*)d_in[9];
    const float* Wih1f = (const float*)d_in[10];
    const float* Whh1f = (const float*)d_in[11];
    const float* b1f   = (const float*)d_in[12];
    const float* Wih1b = (const float*)d_in[13];
    const float* Whh1b = (const float*)d_in[14];
    const float* b1b   = (const float*)d_in[15];
    const float* Wout  = (const float*)d_in[16];
    const float* bout  = (const float*)d_in[17];
    const float* start_t = (const float*)d_in[18];
    const float* end_t   = (const float*)d_in[19];
    const float* trans   = (const float*)d_in[20];
    float* out = (float*)d_out;

    float *x0, *gxf, *gxb, *h1, *h2, *emitb, *scr;
    cudaGetSymbolAddress((void**)&x0, g_x0);
    cudaGetSymbolAddress((void**)&gxf, g_gxf);
    cudaGetSymbolAddress((void**)&gxb, g_gxb);
    cudaGetSymbolAddress((void**)&h1, g_h1);
    cudaGetSymbolAddress((void**)&h2, g_h2);
    cudaGetSymbolAddress((void**)&emitb, g_emit);
    cudaGetSymbolAddress((void**)&scr, g_scr);

    cudaFuncSetAttribute(lstm_layer, cudaFuncAttributeMaxDynamicSharedMemorySize,
                         L_TOTAL);
    cudaFuncSetAttribute(mma_gemm, cudaFuncAttributeMaxDynamicSharedMemorySize,
                         MG_TOTAL);

    embed_kernel<<<ROWS_TB, 256>>>(sentence, embed, x0);

    // layer 0
    mma_gemm<<<dim3(16, 64, 2), 256, MG_TOTAL>>>(
        x0, Wih0f, Wih0b, b0f, b0b, gxf, gxb, 256, GATES);
    lstm_reset<<<128, 256>>>();
    lstm_layer<<<128, 256, L_TOTAL>>>(gxf, gxb, Whh0f, Whh0b, lengths, h1);

    // layer 1
    mma_gemm<<<dim3(16, 64, 2), 256, MG_TOTAL>>>(
        h1, Wih1f, Wih1b, b1f, b1b, gxf, gxb, 512, GATES);
    lstm_reset<<<128, 256>>>();
    lstm_layer<<<128, 256, L_TOTAL>>>(gxf, gxb, Whh1f, Whh1b, lengths, h2);

    // emissions
    mma_gemm<<<dim3(1, 64, 1), 256, MG_TOTAL>>>(
        h2, Wout, Wout, bout, bout, emitb, emitb, 512, KK);

    finalize_kernel<<<BB * TT, 64>>>(emitb, sentence, out, out_size);
    crf_kernel<<<BB, 64>>>(emitb, tags, lengths, start_t, end_t, trans, scr);
    loss_kernel<<<1, 32>>>(scr, out, out_size);
}

// round 12
// speedup vs baseline: 1.9032x; 1.9032x over previous
#include <cuda_runtime.h>
#include <cuda_bf16.h>
#include <cstdint>
#include <math.h>

#define TT 256
#define BB 32
#define HH 256
#define KK 48
#define GATES 1024          // 4*H
#define ROWS_TB (TT*BB)     // 8192

// ---------------- device scratch (no allocations allowed) ----------------
__device__ float g_x0[ROWS_TB * 256];        // embedded input (t,b,e)
__device__ float g_gxf[ROWS_TB * GATES];     // x@Wih^T + b, fwd
__device__ float g_gxb[ROWS_TB * GATES];     // x@Wih^T + b, bwd
__device__ float g_h1[ROWS_TB * 512];        // layer-0 output (hf|hb)
__device__ float g_h2[ROWS_TB * 512];        // layer-1 output
__device__ float g_emit[ROWS_TB * KK];       // emissions (t,b,k)
__device__ float g_scr[BB];                  // per-batch (num-den)

// L2-exchange: h[par][dir][bg][b*256+u], flags [dir][bg][rank] (counters, +128/step)
__device__ float g_hx[2 * 2 * 8 * 1024];     // 128 KB
__device__ int   g_flag[2 * 8 * 8];          // 128 ints

// output layout: [emit (B,T,K) fp32 | loss | mask (B,T)]
#define EMIT_N   (BB*TT*KK)      // 393216
#define LOSS_OFF EMIT_N
#define MASK_OFF (EMIT_N + 1)

// ---------------- helpers ----------------
__device__ __forceinline__ float sigf(float x) { return 1.0f / (1.0f + __expf(-x)); }

__device__ __forceinline__ uint32_t smem_u32(const void* p) {
    uint32_t a;
    asm("{ .reg .u64 t; cvta.to.shared.u64 t, %1; cvt.u32.u64 %0, t; }" : "=r"(a) : "l"(p));
    return a;
}
// pack (lo half = a, hi half = b) into bf16x2
__device__ __forceinline__ uint32_t pk2(float a, float b) {
    uint32_t r;
    asm("cvt.rn.bf16x2.f32 %0, %1, %2;" : "=r"(r) : "f"(b), "f"(a));
    return r;
}
__device__ __forceinline__ void ldm_x4(uint32_t* r, uint32_t addr) {
    asm volatile("ldmatrix.sync.aligned.m8n8.x4.shared.b16 {%0,%1,%2,%3}, [%4];"
                 : "=r"(r[0]), "=r"(r[1]), "=r"(r[2]), "=r"(r[3]) : "r"(addr));
}
__device__ __forceinline__ void ldm_x2(uint32_t* r, uint32_t addr) {
    asm volatile("ldmatrix.sync.aligned.m8n8.x2.shared.b16 {%0,%1}, [%2];"
                 : "=r"(r[0]), "=r"(r[1]) : "r"(addr));
}
__device__ __forceinline__ void mma16816(float* c, const uint32_t* a, const uint32_t* b) {
    asm volatile("mma.sync.aligned.m16n8k16.row.col.f32.bf16.bf16.f32 "
                 "{%0,%1,%2,%3}, {%4,%5,%6,%7}, {%8,%9}, {%0,%1,%2,%3};"
                 : "+f"(c[0]), "+f"(c[1]), "+f"(c[2]), "+f"(c[3])
                 : "r"(a[0]), "r"(a[1]), "r"(a[2]), "r"(a[3]), "r"(b[0]), "r"(b[1]));
}
__device__ __forceinline__ int ld_acq(const int* p) {
    int v;
    asm volatile("ld.acquire.gpu.global.s32 %0, [%1];" : "=r"(v) : "l"(p) : "memory");
    return v;
}
// per-producer release-increment on the step counter: orders this thread's
// prior global stores (the h publish) before the increment, no block fence.
__device__ __forceinline__ void red_add_release(int* p, int v) {
    asm volatile("red.release.gpu.global.add.s32 [%0], %1;" :: "l"(p), "r"(v) : "memory");
}

// ---------------- embedding gather ----------------
__global__ void embed_kernel(const int* __restrict__ sent,
                             const float* __restrict__ embed,
                             float* __restrict__ x0) {
    int bid = blockIdx.x;            // t*32 + b
    int t = bid >> 5, b = bid & 31;
    int tok = sent[b * TT + t];
    x0[(size_t)bid * 256 + threadIdx.x] = embed[(size_t)tok * 256 + threadIdx.x];
}

// ---------------- mma.sync bf16x3 GEMM: C[M,N] = A[M,K] * W[N,K]^T + bias ----------------
#define MG_AHI 0
#define MG_ALO 18432
#define MG_BHI 36864
#define MG_BLO 46080
#define MG_TOTAL 55296
#define APITCH 72

__global__ void __launch_bounds__(256)
mma_gemm(const float* __restrict__ A,
         const float* __restrict__ Wf, const float* __restrict__ Wb,
         const float* __restrict__ biasf, const float* __restrict__ biasb,
         float* __restrict__ Cf, float* __restrict__ Cb,
         int K, int Nout) {
    extern __shared__ char smc[];
    uint32_t sb = smem_u32(smc);
    int tid = threadIdx.x, wid = tid >> 5, l = tid & 31;
    int m0 = blockIdx.y * 128, n0 = blockIdx.x * 64;
    const float* W    = blockIdx.z ? Wb : Wf;
    const float* bias = blockIdx.z ? biasb : biasf;
    float*       C    = blockIdx.z ? Cb : Cf;

    int wm = wid & 3, wn = wid >> 2;
    int srow = tid >> 4;
    int scol = (tid & 15) << 2;

    float c[2][4][4];
#pragma unroll
    for (int mi = 0; mi < 2; mi++)
#pragma unroll
        for (int ni = 0; ni < 4; ni++)
#pragma unroll
            for (int j = 0; j < 4; j++) c[mi][ni][j] = 0.0f;

    int nch = K >> 6;
    for (int ch = 0; ch < nch; ch++) {
        int kc = ch << 6;
#pragma unroll
        for (int rr = 0; rr < 8; rr++) {
            int row = srow + rr * 16;
            float4 v = *(const float4*)&A[(size_t)(m0 + row) * K + kc + scol];
            float hx = __bfloat162float(__float2bfloat16(v.x));
            float hy = __bfloat162float(__float2bfloat16(v.y));
            float hz = __bfloat162float(__float2bfloat16(v.z));
            float hw = __bfloat162float(__float2bfloat16(v.w));
            uint32_t off = (uint32_t)(row * APITCH + scol) * 2;
            *(uint2*)(smc + MG_AHI + off) = make_uint2(pk2(hx, hy), pk2(hz, hw));
            *(uint2*)(smc + MG_ALO + off) =
                make_uint2(pk2(v.x - hx, v.y - hy), pk2(v.z - hz, v.w - hw));
        }
#pragma unroll
        for (int rr = 0; rr < 4; rr++) {
            int row = srow + rr * 16;
            int n = n0 + row;
            float4 v = make_float4(0.f, 0.f, 0.f, 0.f);
            if (n < Nout) v = *(const float4*)&W[(size_t)n * K + kc + scol];
            float hx = __bfloat162float(__float2bfloat16(v.x));
            float hy = __bfloat162float(__float2bfloat16(v.y));
            float hz = __bfloat162float(__float2bfloat16(v.z));
            float hw = __bfloat162float(__float2bfloat16(v.w));
            uint32_t off = (uint32_t)(row * APITCH + scol) * 2;
            *(uint2*)(smc + MG_BHI + off) = make_uint2(pk2(hx, hy), pk2(hz, hw));
            *(uint2*)(smc + MG_BLO + off) =
                make_uint2(pk2(v.x - hx, v.y - hy), pk2(v.z - hz, v.w - hw));
        }
        __syncthreads();

#pragma unroll
        for (int ks = 0; ks < 4; ks++) {
            uint32_t ah[2][4], al[2][4];
#pragma unroll
            for (int mi = 0; mi < 2; mi++) {
                uint32_t off =
                    (uint32_t)((wm * 32 + mi * 16 + (l & 15)) * APITCH +
                               ks * 16 + (l >> 4) * 8) * 2;
                ldm_x4(ah[mi], sb + MG_AHI + off);
                ldm_x4(al[mi], sb + MG_ALO + off);
            }
            uint32_t bh[4][2], bl[4][2];
#pragma unroll
            for (int ni = 0; ni < 4; ni++) {
                uint32_t off =
                    (uint32_t)((wn * 32 + ni * 8 + (l & 7)) * APITCH +
                               ks * 16 + ((l >> 3) & 1) * 8) * 2;
                ldm_x2(bh[ni], sb + MG_BHI + off);
                ldm_x2(bl[ni], sb + MG_BLO + off);
            }
#pragma unroll
            for (int mi = 0; mi < 2; mi++)
#pragma unroll
                for (int ni = 0; ni < 4; ni++) {
                    mma16816(c[mi][ni], ah[mi], bh[ni]);
                    mma16816(c[mi][ni], al[mi], bh[ni]);
                    mma16816(c[mi][ni], ah[mi], bl[ni]);
                }
        }
        __syncthreads();
    }

#pragma unroll
    for (int mi = 0; mi < 2; mi++) {
#pragma unroll
        for (int ni = 0; ni < 4; ni++) {
#pragma unroll
            for (int j = 0; j < 4; j++) {
                int row = m0 + wm * 32 + mi * 16 + (l >> 2) + (j >> 1) * 8;
                int col = n0 + wn * 32 + ni * 8 + (l & 3) * 2 + (j & 1);
                if (col < Nout)
                    C[(size_t)row * Nout + col] = c[mi][ni][j] + bias[col];
            }
        }
    }
}

// ---------------- reset for the L2-exchange state (run before each lstm launch) ----
__global__ void lstm_reset() {
    int idx = blockIdx.x * blockDim.x + threadIdx.x;
    if (idx < 2 * 2 * 8 * 1024) g_hx[idx] = 0.0f;
    if (idx < 2 * 8 * 8) g_flag[idx] = 0;
}

// ---------------- BiLSTM layer v8: v5b + latency surgery ----------------
// Changes vs v5b (R9, best at 2960us):
//  1. Hout DRAM store moved AFTER signaling (fence no longer waits on DRAM).
//  2. Per-producer red.release.gpu.add on the per-rank flag counter (consumer
//     waits flag >= 128*s); no __threadfence, no tid0 flag store.
//  3. Trailing __syncthreads removed (next iteration's post-copy sync covers
//     gsm/red reuse; copy targets the opposite parity buffer).
#define WPITCH 132
#define OFF_WHHT 0
#define OFF_HBUF (256 * WPITCH)                  // 33792 floats
#define OFF_RED  (OFF_HBUF + 2048)               // 35840
#define OFF_GSM  (OFF_RED + 512)                 // 36352
#define OFF_CSM  (OFF_GSM + 512)                 // 36864
#define LSTM_SMEM_FLOATS (OFF_CSM + 128)         // 36992
#define LSTM_SMEM_BYTES  (LSTM_SMEM_FLOATS * 4)  // 147968

__global__ void __launch_bounds__(256, 1)
lstm_layer(const float* __restrict__ GxF, const float* __restrict__ GxB,
           const float* __restrict__ WhhF, const float* __restrict__ WhhB,
           const int* __restrict__ lengths, float* __restrict__ Hout) {
    extern __shared__ float sm[];
    float* WhhT = sm + OFF_WHHT;
    float* hbuf = sm + OFF_HBUF;
    float* red  = sm + OFF_RED;
    float* gsm  = sm + OFF_GSM;
    float* csm  = sm + OFF_CSM;

    int tid = threadIdx.x;
    int l   = tid & 31;
    int r   = blockIdx.x & 7;
    int cid = blockIdx.x >> 3;
    int dir = cid >> 3;
    int bg  = cid & 7;
    int batch0 = bg * 4;

    const float* Gx  = dir ? GxB : GxF;
    const float* Whh = dir ? WhhB : WhhF;

    float* hx_base  = g_hx;                       // [par][dir][bg][1024]
    int*   flg_base = g_flag + (dir * 8 + bg) * 8;

    // stage Whh slice transposed (fp32): WhhT[k][g]
    for (int idx = tid; idx < 128 * 256; idx += 256) {
        int g = idx >> 8;
        int k = idx & 255;
        int q = g >> 5, u = g & 31;
        WhhT[k * WPITCH + g] = Whh[(size_t)((q << 8) + (r << 5) + u) * 256 + k];
    }
    if (tid < 128) csm[tid] = 0.0f;
    __syncthreads();

    int g  = tid & 127;
    int kh = tid >> 7;
    int kbase = kh << 7;
    int grow = ((g >> 5) << 8) + (r << 5) + (g & 31);

    int b2 = tid >> 5, uu = tid & 31;        // producer mapping (tid<128)
    int mylen = 0;
    if (tid < 128) mylen = lengths[batch0 + b2];
    float hreg = 0.0f;

    for (int s = 0; s < TT; ++s) {
        int t = dir ? (TT - 1 - s) : s;
        int par = s & 1;

        // prefetch gate-x for this step before polling (hide DRAM/L2)
        float gx0 = 0.f, gx1 = 0.f, gx2 = 0.f, gx3 = 0.f;
        if (kh == 0) {
            const float* gp = Gx + ((size_t)t * BB + batch0) * GATES + grow;
            gx0 = gp[0]; gx1 = gp[GATES]; gx2 = gp[2 * GATES]; gx3 = gp[3 * GATES];
        }

        // wait for all 8 ranks' h slices: each rank adds 128 per step
        if (s > 0) {
            int need = 128 * s;
            for (;;) {
                bool ok = (l < 8) ? (ld_acq(flg_base + l) >= need) : true;
                if (__all_sync(0xffffffffu, ok)) break;
            }
        }

        // copy full h (1024 floats) L2 -> smem[par]
        {
            const float4* src = (const float4*)(hx_base + ((par * 2 + dir) * 8 + bg) * 1024);
            float4 v = __ldcg(src + tid);
            *(float4*)&hbuf[par * 1024 + tid * 4] = v;
        }
        __syncthreads();

        const float* hb0 = hbuf + par * 1024 + kbase;
        const float* hb1 = hb0 + 256;
        const float* hb2 = hb0 + 512;
        const float* hb3 = hb0 + 768;
        const float* wp  = WhhT + kbase * WPITCH + g;

        float a0 = 0.f, a1 = 0.f, a2 = 0.f, a3 = 0.f;
#pragma unroll 8
        for (int k = 0; k < 128; k += 4) {
            float4 h0 = *(const float4*)(hb0 + k);
            float4 h1 = *(const float4*)(hb1 + k);
            float4 h2 = *(const float4*)(hb2 + k);
            float4 h3 = *(const float4*)(hb3 + k);
            float w0 = wp[(k + 0) * WPITCH];
            float w1 = wp[(k + 1) * WPITCH];
            float w2 = wp[(k + 2) * WPITCH];
            float w3 = wp[(k + 3) * WPITCH];
            a0 += w0 * h0.x; a0 += w1 * h0.y; a0 += w2 * h0.z; a0 += w3 * h0.w;
            a1 += w0 * h1.x; a1 += w1 * h1.y; a1 += w2 * h1.z; a1 += w3 * h1.w;
            a2 += w0 * h2.x; a2 += w1 * h2.y; a2 += w2 * h2.z; a2 += w3 * h2.w;
            a3 += w0 * h3.x; a3 += w1 * h3.y; a3 += w2 * h3.z; a3 += w3 * h3.w;
        }

        if (kh) {
            red[g * 4 + 0] = a0; red[g * 4 + 1] = a1;
            red[g * 4 + 2] = a2; red[g * 4 + 3] = a3;
        }
        __syncthreads();
        if (!kh) {
            int q = g >> 5, u = g & 31;
            float t0 = a0 + red[g * 4 + 0] + gx0;
            float t1 = a1 + red[g * 4 + 1] + gx1;
            float t2 = a2 + red[g * 4 + 2] + gx2;
            float t3 = a3 + red[g * 4 + 3] + gx3;
            gsm[(0 * 4 + q) * 32 + u] = t0;
            gsm[(1 * 4 + q) * 32 + u] = t1;
            gsm[(2 * 4 + q) * 32 + u] = t2;
            gsm[(3 * 4 + q) * 32 + u] = t3;
        }
        __syncthreads();

        if (tid < 128) {
            float iv = gsm[(b2 * 4 + 0) * 32 + uu];
            float fv = gsm[(b2 * 4 + 1) * 32 + uu];
            float gv = gsm[(b2 * 4 + 2) * 32 + uu];
            float ov = gsm[(b2 * 4 + 3) * 32 + uu];
            float c  = csm[b2 * 32 + uu];
            float c2 = sigf(fv) * c + sigf(iv) * tanhf(gv);
            float h2 = sigf(ov) * tanhf(c2);
            bool m = (t < mylen);
            float hn = m ? h2 : hreg;
            float cn = m ? c2 : c;
            csm[b2 * 32 + uu] = cn;
            hreg = hn;

            if (s < TT - 1) {
                // publish own slice for step s+1, then release-increment the
                // flag counter (orders THIS thread's h store before the add)
                hx_base[(((par ^ 1) * 2 + dir) * 8 + bg) * 1024 +
                        (b2 << 8) + (r << 5) + uu] = hn;
                red_add_release(flg_base + r, 1);
            }
            // Hout (DRAM) AFTER signaling — off the critical path
            Hout[((size_t)t * BB + batch0 + b2) * 512 + dir * 256 + (r << 5) + uu] =
                m ? h2 : 0.0f;
        }
        // no trailing syncthreads: next iteration's post-copy sync covers
        // gsm/red reuse (copy writes the opposite parity hbuf half)
    }
}

// ---------------- emit transpose + mask output ----------------
__global__ void finalize_kernel(const float* __restrict__ emitb,
                                const int* __restrict__ sent,
                                float* __restrict__ out, int out_size) {
    int bid = blockIdx.x;            // b*256 + t
    int b = bid >> 8, t = bid & 255;
    int k = threadIdx.x;
    if (k < KK) out[(size_t)bid * KK + k] = emitb[((size_t)t * BB + b) * KK + k];
    if (k == KK) {
        int idx = MASK_OFF + bid;
        if (idx < out_size) out[idx] = (sent[bid] != 0) ? 1.0f : 0.0f;
    }
}

// ---------------- CRF ----------------
__global__ void crf_kernel(const float* __restrict__ emitb,
                           const int* __restrict__ tags,
                           const int* __restrict__ lengths,
                           const float* __restrict__ start_t,
                           const float* __restrict__ end_t,
                           const float* __restrict__ trans,
                           float* __restrict__ scratch) {
    int b = blockIdx.x;
    int tid = threadIdx.x;           // 64
    __shared__ float trs[KK * KK];
    __shared__ float score[KK];
    __shared__ float nsc[KK];
    __shared__ float rbuf[64];
    __shared__ float numsh;

    for (int i = tid; i < KK * KK; i += 64) trs[i] = trans[i];
    int len = lengths[b];
    __syncthreads();

    float part = 0.0f;
    for (int t = 1 + tid; t < len; t += 64) {
        int tg = tags[b * TT + t];
        int pg = tags[b * TT + t - 1];
        part += trs[pg * KK + tg] + emitb[((size_t)t * BB + b) * KK + tg];
    }
    rbuf[tid] = part;
    __syncthreads();
    for (int s = 32; s > 0; s >>= 1) {
        if (tid < s) rbuf[tid] += rbuf[tid + s];
        __syncthreads();
    }
    if (tid == 0) {
        int t0 = tags[b * TT + 0];
        numsh = rbuf[0] + start_t[t0] + emitb[(size_t)b * KK + t0]
              + end_t[tags[b * TT + len - 1]];
    }

    if (tid < KK) score[tid] = start_t[tid] + emitb[(size_t)b * KK + tid];
    __syncthreads();
    for (int t = 1; t < len; t++) {
        if (tid < KK) {
            int k = tid;
            float m = -1e30f;
#pragma unroll 4
            for (int j = 0; j < KK; j++) {
                float v = score[j] + trs[j * KK + k];
                m = fmaxf(m, v);
            }
            float ssum = 0.0f;
#pragma unroll 4
            for (int j = 0; j < KK; j++)
                ssum += expf(score[j] + trs[j * KK + k] - m);
            nsc[k] = m + logf(ssum) + emitb[((size_t)t * BB + b) * KK + k];
        }
        __syncthreads();
        if (tid < KK) score[tid] = nsc[tid];
        __syncthreads();
    }
    if (tid == 0) {
        float m = -1e30f;
        for (int k = 0; k < KK; k++) m = fmaxf(m, score[k] + end_t[k]);
        float ssum = 0.0f;
        for (int k = 0; k < KK; k++) ssum += expf(score[k] + end_t[k] - m);
        float den = m + logf(ssum);
        scratch[b] = numsh - den;
    }
}

__global__ void loss_kernel(const float* __restrict__ scratch,
                            float* __restrict__ out, int out_size) {
    if (threadIdx.x == 0 && LOSS_OFF < out_size) {
        float s = 0.0f;
        for (int b = 0; b < BB; b++) s += scratch[b];
        out[LOSS_OFF] = s / (float)BB;
    }
}

// ---------------- launch ----------------
extern "C" void kernel_launch(void* const* d_in, const int* in_sizes, int n_in,
                              void* d_out, int out_size) {
    const int*   sentence = (const int*)d_in[0];
    const int*   lengths  = (const int*)d_in[1];
    const int*   tags     = (const int*)d_in[2];
    const float* embed    = (const float*)d_in[3];
    const float* Wih0f = (const float*)d_in[4];
    const float* Whh0f = (const float*)d_in[5];
    const float* b0f   = (const float*)d_in[6];
    const float* Wih0b = (const float*)d_in[7];
    const float* Whh0b = (const float*)d_in[8];
    const float* b0b   = (const float*)d_in[9];
    const float* Wih1f = (const float*)d_in[10];
    const float* Whh1f = (const float*)d_in[11];
    const float* b1f   = (const float*)d_in[12];
    const float* Wih1b = (const float*)d_in[13];
    const float* Whh1b = (const float*)d_in[14];
    const float* b1b   = (const float*)d_in[15];
    const float* Wout  = (const float*)d_in[16];
    const float* bout  = (const float*)d_in[17];
    const float* start_t = (const float*)d_in[18];
    const float* end_t   = (const float*)d_in[19];
    const float* trans   = (const float*)d_in[20];
    float* out = (float*)d_out;

    float *x0, *gxf, *gxb, *h1, *h2, *emitb, *scr;
    cudaGetSymbolAddress((void**)&x0, g_x0);
    cudaGetSymbolAddress((void**)&gxf, g_gxf);
    cudaGetSymbolAddress((void**)&gxb, g_gxb);
    cudaGetSymbolAddress((void**)&h1, g_h1);
    cudaGetSymbolAddress((void**)&h2, g_h2);
    cudaGetSymbolAddress((void**)&emitb, g_emit);
    cudaGetSymbolAddress((void**)&scr, g_scr);

    cudaFuncSetAttribute(lstm_layer, cudaFuncAttributeMaxDynamicSharedMemorySize,
                         LSTM_SMEM_BYTES);
    cudaFuncSetAttribute(mma_gemm, cudaFuncAttributeMaxDynamicSharedMemorySize,
                         MG_TOTAL);

    embed_kernel<<<ROWS_TB, 256>>>(sentence, embed, x0);

    // layer 0
    mma_gemm<<<dim3(16, 64, 2), 256, MG_TOTAL>>>(
        x0, Wih0f, Wih0b, b0f, b0b, gxf, gxb, 256, GATES);
    lstm_reset<<<128, 256>>>();
    lstm_layer<<<128, 256, LSTM_SMEM_BYTES>>>(gxf, gxb, Whh0f, Whh0b, lengths, h1);

    // layer 1
    mma_gemm<<<dim3(16, 64, 2), 256, MG_TOTAL>>>(
        h1, Wih1f, Wih1b, b1f, b1b, gxf, gxb, 512, GATES);
    lstm_reset<<<128, 256>>>();
    lstm_layer<<<128, 256, LSTM_SMEM_BYTES>>>(gxf, gxb, Whh1f, Whh1b, lengths, h2);

    // emissions
    mma_gemm<<<dim3(1, 64, 1), 256, MG_TOTAL>>>(
        h2, Wout, Wout, bout, bout, emitb, emitb, 512, KK);

    finalize_kernel<<<BB * TT, 64>>>(emitb, sentence, out, out_size);
    crf_kernel<<<BB, 64>>>(emitb, tags, lengths, start_t, end_t, trans, scr);
    loss_kernel<<<1, 32>>>(scr, out, out_size);
}

// round 13
// speedup vs baseline: 1.9881x; 1.0446x over previous
#include <cuda_runtime.h>
#include <cuda_bf16.h>
#include <cstdint>
#include <math.h>

#define TT 256
#define BB 32
#define HH 256
#define KK 48
#define GATES 1024          // 4*H
#define ROWS_TB (TT*BB)     // 8192

// ---------------- device scratch (no allocations allowed) ----------------
__device__ float g_x0[ROWS_TB * 256];        // embedded input (t,b,e)
__device__ float g_gxf[ROWS_TB * GATES];     // x@Wih^T + b, fwd
__device__ float g_gxb[ROWS_TB * GATES];     // x@Wih^T + b, bwd
__device__ float g_h1[ROWS_TB * 512];        // layer-0 output (hf|hb)
__device__ float g_h2[ROWS_TB * 512];        // layer-1 output
__device__ float g_emit[ROWS_TB * KK];       // emissions (t,b,k)
__device__ float g_scr[BB];                  // per-batch (num-den)

// L2-exchange: h[par][dir][bg][b*256+u], flags [dir][bg][rank] (counters, +128/step)
__device__ float g_hx[2 * 2 * 8 * 1024];     // 128 KB
__device__ int   g_flag[2 * 8 * 8];          // 128 ints

// output layout: [emit (B,T,K) fp32 | loss | mask (B,T)]
#define EMIT_N   (BB*TT*KK)      // 393216
#define LOSS_OFF EMIT_N
#define MASK_OFF (EMIT_N + 1)

// ---------------- helpers ----------------
__device__ __forceinline__ float sigf(float x) { return 1.0f / (1.0f + __expf(-x)); }
__device__ __forceinline__ float tanh_fast(float x) {
    return 2.0f / (1.0f + __expf(-2.0f * x)) - 1.0f;
}

__device__ __forceinline__ uint32_t smem_u32(const void* p) {
    uint32_t a;
    asm("{ .reg .u64 t; cvta.to.shared.u64 t, %1; cvt.u32.u64 %0, t; }" : "=r"(a) : "l"(p));
    return a;
}
// pack (lo half = a, hi half = b) into bf16x2
__device__ __forceinline__ uint32_t pk2(float a, float b) {
    uint32_t r;
    asm("cvt.rn.bf16x2.f32 %0, %1, %2;" : "=r"(r) : "f"(b), "f"(a));
    return r;
}
__device__ __forceinline__ void ldm_x4(uint32_t* r, uint32_t addr) {
    asm volatile("ldmatrix.sync.aligned.m8n8.x4.shared.b16 {%0,%1,%2,%3}, [%4];"
                 : "=r"(r[0]), "=r"(r[1]), "=r"(r[2]), "=r"(r[3]) : "r"(addr));
}
__device__ __forceinline__ void ldm_x2(uint32_t* r, uint32_t addr) {
    asm volatile("ldmatrix.sync.aligned.m8n8.x2.shared.b16 {%0,%1}, [%2];"
                 : "=r"(r[0]), "=r"(r[1]) : "r"(addr));
}
__device__ __forceinline__ void mma16816(float* c, const uint32_t* a, const uint32_t* b) {
    asm volatile("mma.sync.aligned.m16n8k16.row.col.f32.bf16.bf16.f32 "
                 "{%0,%1,%2,%3}, {%4,%5,%6,%7}, {%8,%9}, {%0,%1,%2,%3};"
                 : "+f"(c[0]), "+f"(c[1]), "+f"(c[2]), "+f"(c[3])
                 : "r"(a[0]), "r"(a[1]), "r"(a[2]), "r"(a[3]), "r"(b[0]), "r"(b[1]));
}
__device__ __forceinline__ int ld_acq(const int* p) {
    int v;
    asm volatile("ld.acquire.gpu.global.s32 %0, [%1];" : "=r"(v) : "l"(p) : "memory");
    return v;
}
// per-producer release-increment on the step counter: orders this thread's
// prior global stores (the h publish) before the increment, no block fence.
__device__ __forceinline__ void red_add_release(int* p, int v) {
    asm volatile("red.release.gpu.global.add.s32 [%0], %1;" :: "l"(p), "r"(v) : "memory");
}

// ---------------- embedding gather ----------------
__global__ void embed_kernel(const int* __restrict__ sent,
                             const float* __restrict__ embed,
                             float* __restrict__ x0) {
    int bid = blockIdx.x;            // t*32 + b
    int t = bid >> 5, b = bid & 31;
    int tok = sent[b * TT + t];
    x0[(size_t)bid * 256 + threadIdx.x] = embed[(size_t)tok * 256 + threadIdx.x];
}

// ---------------- mma.sync bf16x3 GEMM: C[M,N] = A[M,K] * W[N,K]^T + bias ----------------
#define MG_AHI 0
#define MG_ALO 18432
#define MG_BHI 36864
#define MG_BLO 46080
#define MG_TOTAL 55296
#define APITCH 72

__global__ void __launch_bounds__(256)
mma_gemm(const float* __restrict__ A,
         const float* __restrict__ Wf, const float* __restrict__ Wb,
         const float* __restrict__ biasf, const float* __restrict__ biasb,
         float* __restrict__ Cf, float* __restrict__ Cb,
         int K, int Nout) {
    extern __shared__ char smc[];
    uint32_t sb = smem_u32(smc);
    int tid = threadIdx.x, wid = tid >> 5, l = tid & 31;
    int m0 = blockIdx.y * 128, n0 = blockIdx.x * 64;
    const float* W    = blockIdx.z ? Wb : Wf;
    const float* bias = blockIdx.z ? biasb : biasf;
    float*       C    = blockIdx.z ? Cb : Cf;

    int wm = wid & 3, wn = wid >> 2;
    int srow = tid >> 4;
    int scol = (tid & 15) << 2;

    float c[2][4][4];
#pragma unroll
    for (int mi = 0; mi < 2; mi++)
#pragma unroll
        for (int ni = 0; ni < 4; ni++)
#pragma unroll
            for (int j = 0; j < 4; j++) c[mi][ni][j] = 0.0f;

    int nch = K >> 6;
    for (int ch = 0; ch < nch; ch++) {
        int kc = ch << 6;
#pragma unroll
        for (int rr = 0; rr < 8; rr++) {
            int row = srow + rr * 16;
            float4 v = *(const float4*)&A[(size_t)(m0 + row) * K + kc + scol];
            float hx = __bfloat162float(__float2bfloat16(v.x));
            float hy = __bfloat162float(__float2bfloat16(v.y));
            float hz = __bfloat162float(__float2bfloat16(v.z));
            float hw = __bfloat162float(__float2bfloat16(v.w));
            uint32_t off = (uint32_t)(row * APITCH + scol) * 2;
            *(uint2*)(smc + MG_AHI + off) = make_uint2(pk2(hx, hy), pk2(hz, hw));
            *(uint2*)(smc + MG_ALO + off) =
                make_uint2(pk2(v.x - hx, v.y - hy), pk2(v.z - hz, v.w - hw));
        }
#pragma unroll
        for (int rr = 0; rr < 4; rr++) {
            int row = srow + rr * 16;
            int n = n0 + row;
            float4 v = make_float4(0.f, 0.f, 0.f, 0.f);
            if (n < Nout) v = *(const float4*)&W[(size_t)n * K + kc + scol];
            float hx = __bfloat162float(__float2bfloat16(v.x));
            float hy = __bfloat162float(__float2bfloat16(v.y));
            float hz = __bfloat162float(__float2bfloat16(v.z));
            float hw = __bfloat162float(__float2bfloat16(v.w));
            uint32_t off = (uint32_t)(row * APITCH + scol) * 2;
            *(uint2*)(smc + MG_BHI + off) = make_uint2(pk2(hx, hy), pk2(hz, hw));
            *(uint2*)(smc + MG_BLO + off) =
                make_uint2(pk2(v.x - hx, v.y - hy), pk2(v.z - hz, v.w - hw));
        }
        __syncthreads();

#pragma unroll
        for (int ks = 0; ks < 4; ks++) {
            uint32_t ah[2][4], al[2][4];
#pragma unroll
            for (int mi = 0; mi < 2; mi++) {
                uint32_t off =
                    (uint32_t)((wm * 32 + mi * 16 + (l & 15)) * APITCH +
                               ks * 16 + (l >> 4) * 8) * 2;
                ldm_x4(ah[mi], sb + MG_AHI + off);
                ldm_x4(al[mi], sb + MG_ALO + off);
            }
            uint32_t bh[4][2], bl[4][2];
#pragma unroll
            for (int ni = 0; ni < 4; ni++) {
                uint32_t off =
                    (uint32_t)((wn * 32 + ni * 8 + (l & 7)) * APITCH +
                               ks * 16 + ((l >> 3) & 1) * 8) * 2;
                ldm_x2(bh[ni], sb + MG_BHI + off);
                ldm_x2(bl[ni], sb + MG_BLO + off);
            }
#pragma unroll
            for (int mi = 0; mi < 2; mi++)
#pragma unroll
                for (int ni = 0; ni < 4; ni++) {
                    mma16816(c[mi][ni], ah[mi], bh[ni]);
                    mma16816(c[mi][ni], al[mi], bh[ni]);
                    mma16816(c[mi][ni], ah[mi], bl[ni]);
                }
        }
        __syncthreads();
    }

#pragma unroll
    for (int mi = 0; mi < 2; mi++) {
#pragma unroll
        for (int ni = 0; ni < 4; ni++) {
#pragma unroll
            for (int j = 0; j < 4; j++) {
                int row = m0 + wm * 32 + mi * 16 + (l >> 2) + (j >> 1) * 8;
                int col = n0 + wn * 32 + ni * 8 + (l & 3) * 2 + (j & 1);
                if (col < Nout)
                    C[(size_t)row * Nout + col] = c[mi][ni][j] + bias[col];
            }
        }
    }
}

// ---------------- reset for the L2-exchange state (run before each lstm launch) ----
__global__ void lstm_reset() {
    int idx = blockIdx.x * blockDim.x + threadIdx.x;
    if (idx < 2 * 2 * 8 * 1024) g_hx[idx] = 0.0f;
    if (idx < 2 * 8 * 8) g_flag[idx] = 0;
}

// ---------------- BiLSTM layer v9: R12 (best) + fast tanh in the gate tail ----------
#define WPITCH 132
#define OFF_WHHT 0
#define OFF_HBUF (256 * WPITCH)                  // 33792 floats
#define OFF_RED  (OFF_HBUF + 2048)               // 35840
#define OFF_GSM  (OFF_RED + 512)                 // 36352
#define OFF_CSM  (OFF_GSM + 512)                 // 36864
#define LSTM_SMEM_FLOATS (OFF_CSM + 128)         // 36992
#define LSTM_SMEM_BYTES  (LSTM_SMEM_FLOATS * 4)  // 147968

__global__ void __launch_bounds__(256, 1)
lstm_layer(const float* __restrict__ GxF, const float* __restrict__ GxB,
           const float* __restrict__ WhhF, const float* __restrict__ WhhB,
           const int* __restrict__ lengths, float* __restrict__ Hout) {
    extern __shared__ float sm[];
    float* WhhT = sm + OFF_WHHT;
    float* hbuf = sm + OFF_HBUF;
    float* red  = sm + OFF_RED;
    float* gsm  = sm + OFF_GSM;
    float* csm  = sm + OFF_CSM;

    int tid = threadIdx.x;
    int l   = tid & 31;
    int r   = blockIdx.x & 7;
    int cid = blockIdx.x >> 3;
    int dir = cid >> 3;
    int bg  = cid & 7;
    int batch0 = bg * 4;

    const float* Gx  = dir ? GxB : GxF;
    const float* Whh = dir ? WhhB : WhhF;

    float* hx_base  = g_hx;                       // [par][dir][bg][1024]
    int*   flg_base = g_flag + (dir * 8 + bg) * 8;

    // stage Whh slice transposed (fp32): WhhT[k][g]
    for (int idx = tid; idx < 128 * 256; idx += 256) {
        int g = idx >> 8;
        int k = idx & 255;
        int q = g >> 5, u = g & 31;
        WhhT[k * WPITCH + g] = Whh[(size_t)((q << 8) + (r << 5) + u) * 256 + k];
    }
    if (tid < 128) csm[tid] = 0.0f;
    __syncthreads();

    int g  = tid & 127;
    int kh = tid >> 7;
    int kbase = kh << 7;
    int grow = ((g >> 5) << 8) + (r << 5) + (g & 31);

    int b2 = tid >> 5, uu = tid & 31;        // producer mapping (tid<128)
    int mylen = 0;
    if (tid < 128) mylen = lengths[batch0 + b2];
    float hreg = 0.0f;

    for (int s = 0; s < TT; ++s) {
        int t = dir ? (TT - 1 - s) : s;
        int par = s & 1;

        // prefetch gate-x for this step before polling (hide DRAM/L2)
        float gx0 = 0.f, gx1 = 0.f, gx2 = 0.f, gx3 = 0.f;
        if (kh == 0) {
            const float* gp = Gx + ((size_t)t * BB + batch0) * GATES + grow;
            gx0 = gp[0]; gx1 = gp[GATES]; gx2 = gp[2 * GATES]; gx3 = gp[3 * GATES];
        }

        // wait for all 8 ranks' h slices: each rank adds 128 per step
        if (s > 0) {
            int need = 128 * s;
            for (;;) {
                bool ok = (l < 8) ? (ld_acq(flg_base + l) >= need) : true;
                if (__all_sync(0xffffffffu, ok)) break;
            }
        }

        // copy full h (1024 floats) L2 -> smem[par]
        {
            const float4* src = (const float4*)(hx_base + ((par * 2 + dir) * 8 + bg) * 1024);
            float4 v = __ldcg(src + tid);
            *(float4*)&hbuf[par * 1024 + tid * 4] = v;
        }
        __syncthreads();

        const float* hb0 = hbuf + par * 1024 + kbase;
        const float* hb1 = hb0 + 256;
        const float* hb2 = hb0 + 512;
        const float* hb3 = hb0 + 768;
        const float* wp  = WhhT + kbase * WPITCH + g;

        float a0 = 0.f, a1 = 0.f, a2 = 0.f, a3 = 0.f;
#pragma unroll 8
        for (int k = 0; k < 128; k += 4) {
            float4 h0 = *(const float4*)(hb0 + k);
            float4 h1 = *(const float4*)(hb1 + k);
            float4 h2 = *(const float4*)(hb2 + k);
            float4 h3 = *(const float4*)(hb3 + k);
            float w0 = wp[(k + 0) * WPITCH];
            float w1 = wp[(k + 1) * WPITCH];
            float w2 = wp[(k + 2) * WPITCH];
            float w3 = wp[(k + 3) * WPITCH];
            a0 += w0 * h0.x; a0 += w1 * h0.y; a0 += w2 * h0.z; a0 += w3 * h0.w;
            a1 += w0 * h1.x; a1 += w1 * h1.y; a1 += w2 * h1.z; a1 += w3 * h1.w;
            a2 += w0 * h2.x; a2 += w1 * h2.y; a2 += w2 * h2.z; a2 += w3 * h2.w;
            a3 += w0 * h3.x; a3 += w1 * h3.y; a3 += w2 * h3.z; a3 += w3 * h3.w;
        }

        if (kh) {
            red[g * 4 + 0] = a0; red[g * 4 + 1] = a1;
            red[g * 4 + 2] = a2; red[g * 4 + 3] = a3;
        }
        __syncthreads();
        if (!kh) {
            int q = g >> 5, u = g & 31;
            float t0 = a0 + red[g * 4 + 0] + gx0;
            float t1 = a1 + red[g * 4 + 1] + gx1;
            float t2 = a2 + red[g * 4 + 2] + gx2;
            float t3 = a3 + red[g * 4 + 3] + gx3;
            gsm[(0 * 4 + q) * 32 + u] = t0;
            gsm[(1 * 4 + q) * 32 + u] = t1;
            gsm[(2 * 4 + q) * 32 + u] = t2;
            gsm[(3 * 4 + q) * 32 + u] = t3;
        }
        __syncthreads();

        if (tid < 128) {
            float iv = gsm[(b2 * 4 + 0) * 32 + uu];
            float fv = gsm[(b2 * 4 + 1) * 32 + uu];
            float gv = gsm[(b2 * 4 + 2) * 32 + uu];
            float ov = gsm[(b2 * 4 + 3) * 32 + uu];
            float c  = csm[b2 * 32 + uu];
            // FAST tail: MUFU-based tanh (validated rel_err ~7e-6 in R5)
            float c2 = sigf(fv) * c + sigf(iv) * tanh_fast(gv);
            float h2 = sigf(ov) * tanh_fast(c2);
            bool m = (t < mylen);
            float hn = m ? h2 : hreg;
            float cn = m ? c2 : c;
            csm[b2 * 32 + uu] = cn;
            hreg = hn;

            if (s < TT - 1) {
                // publish own slice for step s+1, then release-increment the
                // flag counter (orders THIS thread's h store before the add)
                hx_base[(((par ^ 1) * 2 + dir) * 8 + bg) * 1024 +
                        (b2 << 8) + (r << 5) + uu] = hn;
                red_add_release(flg_base + r, 1);
            }
            // Hout (DRAM) AFTER signaling — off the critical path
            Hout[((size_t)t * BB + batch0 + b2) * 512 + dir * 256 + (r << 5) + uu] =
                m ? h2 : 0.0f;
        }
        // no trailing syncthreads: next iteration's post-copy sync covers
        // gsm/red reuse (copy writes the opposite parity hbuf half)
    }
}

// ---------------- emit transpose + mask output ----------------
__global__ void finalize_kernel(const float* __restrict__ emitb,
                                const int* __restrict__ sent,
                                float* __restrict__ out, int out_size) {
    int bid = blockIdx.x;            // b*256 + t
    int b = bid >> 8, t = bid & 255;
    int k = threadIdx.x;
    if (k < KK) out[(size_t)bid * KK + k] = emitb[((size_t)t * BB + b) * KK + k];
    if (k == KK) {
        int idx = MASK_OFF + bid;
        if (idx < out_size) out[idx] = (sent[bid] != 0) ? 1.0f : 0.0f;
    }
}

// ---------------- CRF v2: 96 threads, 2 threads per tag, fast exp/log ----------------
__global__ void crf_kernel(const float* __restrict__ emitb,
                           const int* __restrict__ tags,
                           const int* __restrict__ lengths,
                           const float* __restrict__ start_t,
                           const float* __restrict__ end_t,
                           const float* __restrict__ trans,
                           float* __restrict__ scratch) {
    int b = blockIdx.x;
    int tid = threadIdx.x;           // 96
    __shared__ float trs[KK * KK];
    __shared__ float score[KK];
    __shared__ float nsc[KK];
    __shared__ float rbuf[64];
    __shared__ float numsh;

    for (int i = tid; i < KK * KK; i += 96) trs[i] = trans[i];
    int len = lengths[b];
    __syncthreads();

    // numerator on threads 0..63 (deterministic fixed-tree reduction)
    if (tid < 64) {
        float part = 0.0f;
        for (int t = 1 + tid; t < len; t += 64) {
            int tg = tags[b * TT + t];
            int pg = tags[b * TT + t - 1];
            part += trs[pg * KK + tg] + emitb[((size_t)t * BB + b) * KK + tg];
        }
        rbuf[tid] = part;
    }
    __syncthreads();
    for (int s = 32; s > 0; s >>= 1) {
        if (tid < s) rbuf[tid] += rbuf[tid + s];
        __syncthreads();
    }
    if (tid == 0) {
        int t0 = tags[b * TT + 0];
        numsh = rbuf[0] + start_t[t0] + emitb[(size_t)b * KK + t0]
              + end_t[tags[b * TT + len - 1]];
    }

    // denominator: forward algorithm, 2 threads per k (j split 24/24)
    int k    = tid >> 1;             // 0..47
    int half = tid & 1;
    int jb   = half * 24;

    if (tid < KK) score[tid] = start_t[tid] + emitb[(size_t)b * KK + tid];
    __syncthreads();
    for (int t = 1; t < len; t++) {
        float m = -1e30f;
#pragma unroll 4
        for (int j = 0; j < 24; j++) {
            float v = score[jb + j] + trs[(jb + j) * KK + k];
            m = fmaxf(m, v);
        }
        float m2 = fmaxf(m, __shfl_xor_sync(0xffffffffu, m, 1));
        float ssum = 0.0f;
#pragma unroll 4
        for (int j = 0; j < 24; j++)
            ssum += __expf(score[jb + j] + trs[(jb + j) * KK + k] - m2);
        ssum += __shfl_xor_sync(0xffffffffu, ssum, 1);
        float nv = m2 + __logf(ssum) + emitb[((size_t)t * BB + b) * KK + k];
        __syncthreads();
        if (half == 0) score[k] = nv;
        __syncthreads();
    }
    if (tid == 0) {
        float m = -1e30f;
        for (int kk2 = 0; kk2 < KK; kk2++) m = fmaxf(m, score[kk2] + end_t[kk2]);
        float ssum = 0.0f;
        for (int kk2 = 0; kk2 < KK; kk2++) ssum += __expf(score[kk2] + end_t[kk2] - m);
        float den = m + __logf(ssum);
        scratch[b] = numsh - den;
    }
}

__global__ void loss_kernel(const float* __restrict__ scratch,
                            float* __restrict__ out, int out_size) {
    if (threadIdx.x == 0 && LOSS_OFF < out_size) {
        float s = 0.0f;
        for (int b = 0; b < BB; b++) s += scratch[b];
        out[LOSS_OFF] = s / (float)BB;
    }
}

// ---------------- launch ----------------
extern "C" void kernel_launch(void* const* d_in, const int* in_sizes, int n_in,
                              void* d_out, int out_size) {
    const int*   sentence = (const int*)d_in[0];
    const int*   lengths  = (const int*)d_in[1];
    const int*   tags     = (const int*)d_in[2];
    const float* embed    = (const float*)d_in[3];
    const float* Wih0f = (const float*)d_in[4];
    const float* Whh0f = (const float*)d_in[5];
    const float* b0f   = (const float*)d_in[6];
    const float* Wih0b = (const float*)d_in[7];
    const float* Whh0b = (const float*)d_in[8];
    const float* b0b   = (const float*)d_in[9];
    const float* Wih1f = (const float*)d_in[10];
    const float* Whh1f = (const float*)d_in[11];
    const float* b1f   = (const float*)d_in[12];
    const float* Wih1b = (const float*)d_in[13];
    const float* Whh1b = (const float*)d_in[14];
    const float* b1b   = (const float*)d_in[15];
    const float* Wout  = (const float*)d_in[16];
    const float* bout  = (const float*)d_in[17];
    const float* start_t = (const float*)d_in[18];
    const float* end_t   = (const float*)d_in[19];
    const float* trans   = (const float*)d_in[20];
    float* out = (float*)d_out;

    float *x0, *gxf, *gxb, *h1, *h2, *emitb, *scr;
    cudaGetSymbolAddress((void**)&x0, g_x0);
    cudaGetSymbolAddress((void**)&gxf, g_gxf);
    cudaGetSymbolAddress((void**)&gxb, g_gxb);
    cudaGetSymbolAddress((void**)&h1, g_h1);
    cudaGetSymbolAddress((void**)&h2, g_h2);
    cudaGetSymbolAddress((void**)&emitb, g_emit);
    cudaGetSymbolAddress((void**)&scr, g_scr);

    cudaFuncSetAttribute(lstm_layer, cudaFuncAttributeMaxDynamicSharedMemorySize,
                         LSTM_SMEM_BYTES);
    cudaFuncSetAttribute(mma_gemm, cudaFuncAttributeMaxDynamicSharedMemorySize,
                         MG_TOTAL);

    embed_kernel<<<ROWS_TB, 256>>>(sentence, embed, x0);

    // layer 0
    mma_gemm<<<dim3(16, 64, 2), 256, MG_TOTAL>>>(
        x0, Wih0f, Wih0b, b0f, b0b, gxf, gxb, 256, GATES);
    lstm_reset<<<128, 256>>>();
    lstm_layer<<<128, 256, LSTM_SMEM_BYTES>>>(gxf, gxb, Whh0f, Whh0b, lengths, h1);

    // layer 1
    mma_gemm<<<dim3(16, 64, 2), 256, MG_TOTAL>>>(
        h1, Wih1f, Wih1b, b1f, b1b, gxf, gxb, 512, GATES);
    lstm_reset<<<128, 256>>>();
    lstm_layer<<<128, 256, LSTM_SMEM_BYTES>>>(gxf, gxb, Whh1f, Whh1b, lengths, h2);

    // emissions
    mma_gemm<<<dim3(1, 64, 1), 256, MG_TOTAL>>>(
        h2, Wout, Wout, bout, bout, emitb, emitb, 512, KK);

    finalize_kernel<<<BB * TT, 64>>>(emitb, sentence, out, out_size);
    crf_kernel<<<BB, 96>>>(emitb, tags, lengths, start_t, end_t, trans, scr);
    loss_kernel<<<1, 32>>>(scr, out, out_size);
}

// round 15
// speedup vs baseline: 2.3359x; 1.1749x over previous
#include <cuda_runtime.h>
#include <cuda_bf16.h>
#include <cstdint>
#include <math.h>

#define TT 256
#define BB 32
#define HH 256
#define KK 48
#define GATES 1024          // 4*H
#define ROWS_TB (TT*BB)     // 8192

// ---------------- device scratch (no allocations allowed) ----------------
__device__ float g_x0[ROWS_TB * 256];        // embedded input (t,b,e)
__device__ float g_gxf[ROWS_TB * GATES];     // x@Wih^T + b, fwd
__device__ float g_gxb[ROWS_TB * GATES];     // x@Wih^T + b, bwd
__device__ float g_h1[ROWS_TB * 512];        // layer-0 output (hf|hb)
__device__ float g_h2[ROWS_TB * 512];        // layer-1 output
__device__ float g_emit[ROWS_TB * KK];       // emissions (t,b,k)
__device__ float g_scr[BB];                  // per-batch (num-den)

// L2-exchange: h[par][dir][bg][b*256+u], flags [dir][bg][rank] (counters, +128/step)
__device__ float g_hx[2 * 2 * 8 * 1024];     // 128 KB
__device__ int   g_flag[2 * 8 * 8];          // 128 ints

// output layout: [emit (B,T,K) fp32 | loss | mask (B,T)]
#define EMIT_N   (BB*TT*KK)      // 393216
#define LOSS_OFF EMIT_N
#define MASK_OFF (EMIT_N + 1)

// ---------------- helpers ----------------
__device__ __forceinline__ float sigf(float x) { return 1.0f / (1.0f + __expf(-x)); }
__device__ __forceinline__ float tanh_fast(float x) {
    return 2.0f / (1.0f + __expf(-2.0f * x)) - 1.0f;
}

__device__ __forceinline__ uint32_t smem_u32(const void* p) {
    uint32_t a;
    asm("{ .reg .u64 t; cvta.to.shared.u64 t, %1; cvt.u32.u64 %0, t; }" : "=r"(a) : "l"(p));
    return a;
}
// pack (lo half = a, hi half = b) into bf16x2
__device__ __forceinline__ uint32_t pk2(float a, float b) {
    uint32_t r;
    asm("cvt.rn.bf16x2.f32 %0, %1, %2;" : "=r"(r) : "f"(b), "f"(a));
    return r;
}
__device__ __forceinline__ void ldm_x4(uint32_t* r, uint32_t addr) {
    asm volatile("ldmatrix.sync.aligned.m8n8.x4.shared.b16 {%0,%1,%2,%3}, [%4];"
                 : "=r"(r[0]), "=r"(r[1]), "=r"(r[2]), "=r"(r[3]) : "r"(addr));
}
__device__ __forceinline__ void ldm_x2(uint32_t* r, uint32_t addr) {
    asm volatile("ldmatrix.sync.aligned.m8n8.x2.shared.b16 {%0,%1}, [%2];"
                 : "=r"(r[0]), "=r"(r[1]) : "r"(addr));
}
__device__ __forceinline__ void mma16816(float* c, const uint32_t* a, const uint32_t* b) {
    asm volatile("mma.sync.aligned.m16n8k16.row.col.f32.bf16.bf16.f32 "
                 "{%0,%1,%2,%3}, {%4,%5,%6,%7}, {%8,%9}, {%0,%1,%2,%3};"
                 : "+f"(c[0]), "+f"(c[1]), "+f"(c[2]), "+f"(c[3])
                 : "r"(a[0]), "r"(a[1]), "r"(a[2]), "r"(a[3]), "r"(b[0]), "r"(b[1]));
}
__device__ __forceinline__ int ld_acq(const int* p) {
    int v;
    asm volatile("ld.acquire.gpu.global.s32 %0, [%1];" : "=r"(v) : "l"(p) : "memory");
    return v;
}
// per-producer release-increment on the step counter: orders this thread's
// prior global stores (the h publish) before the increment, no block fence.
__device__ __forceinline__ void red_add_release(int* p, int v) {
    asm volatile("red.release.gpu.global.add.s32 [%0], %1;" :: "l"(p), "r"(v) : "memory");
}

// ---------------- embedding gather ----------------
__global__ void embed_kernel(const int* __restrict__ sent,
                             const float* __restrict__ embed,
                             float* __restrict__ x0) {
    int bid = blockIdx.x;            // t*32 + b
    int t = bid >> 5, b = bid & 31;
    int tok = sent[b * TT + t];
    x0[(size_t)bid * 256 + threadIdx.x] = embed[(size_t)tok * 256 + threadIdx.x];
}

// ---------------- mma.sync bf16x3 GEMM: C[M,N] = A[M,K] * W[N,K]^T + bias ----------------
#define MG_AHI 0
#define MG_ALO 18432
#define MG_BHI 36864
#define MG_BLO 46080
#define MG_TOTAL 55296
#define APITCH 72

__global__ void __launch_bounds__(256)
mma_gemm(const float* __restrict__ A,
         const float* __restrict__ Wf, const float* __restrict__ Wb,
         const float* __restrict__ biasf, const float* __restrict__ biasb,
         float* __restrict__ Cf, float* __restrict__ Cb,
         int K, int Nout) {
    extern __shared__ char smc[];
    uint32_t sb = smem_u32(smc);
    int tid = threadIdx.x, wid = tid >> 5, l = tid & 31;
    int m0 = blockIdx.y * 128, n0 = blockIdx.x * 64;
    const float* W    = blockIdx.z ? Wb : Wf;
    const float* bias = blockIdx.z ? biasb : biasf;
    float*       C    = blockIdx.z ? Cb : Cf;

    int wm = wid & 3, wn = wid >> 2;
    int srow = tid >> 4;
    int scol = (tid & 15) << 2;

    float c[2][4][4];
#pragma unroll
    for (int mi = 0; mi < 2; mi++)
#pragma unroll
        for (int ni = 0; ni < 4; ni++)
#pragma unroll
            for (int j = 0; j < 4; j++) c[mi][ni][j] = 0.0f;

    int nch = K >> 6;
    for (int ch = 0; ch < nch; ch++) {
        int kc = ch << 6;
#pragma unroll
        for (int rr = 0; rr < 8; rr++) {
            int row = srow + rr * 16;
            float4 v = *(const float4*)&A[(size_t)(m0 + row) * K + kc + scol];
            float hx = __bfloat162float(__float2bfloat16(v.x));
            float hy = __bfloat162float(__float2bfloat16(v.y));
            float hz = __bfloat162float(__float2bfloat16(v.z));
            float hw = __bfloat162float(__float2bfloat16(v.w));
            uint32_t off = (uint32_t)(row * APITCH + scol) * 2;
            *(uint2*)(smc + MG_AHI + off) = make_uint2(pk2(hx, hy), pk2(hz, hw));
            *(uint2*)(smc + MG_ALO + off) =
                make_uint2(pk2(v.x - hx, v.y - hy), pk2(v.z - hz, v.w - hw));
        }
#pragma unroll
        for (int rr = 0; rr < 4; rr++) {
            int row = srow + rr * 16;
            int n = n0 + row;
            float4 v = make_float4(0.f, 0.f, 0.f, 0.f);
            if (n < Nout) v = *(const float4*)&W[(size_t)n * K + kc + scol];
            float hx = __bfloat162float(__float2bfloat16(v.x));
            float hy = __bfloat162float(__float2bfloat16(v.y));
            float hz = __bfloat162float(__float2bfloat16(v.z));
            float hw = __bfloat162float(__float2bfloat16(v.w));
            uint32_t off = (uint32_t)(row * APITCH + scol) * 2;
            *(uint2*)(smc + MG_BHI + off) = make_uint2(pk2(hx, hy), pk2(hz, hw));
            *(uint2*)(smc + MG_BLO + off) =
                make_uint2(pk2(v.x - hx, v.y - hy), pk2(v.z - hz, v.w - hw));
        }
        __syncthreads();

#pragma unroll
        for (int ks = 0; ks < 4; ks++) {
            uint32_t ah[2][4], al[2][4];
#pragma unroll
            for (int mi = 0; mi < 2; mi++) {
                uint32_t off =
                    (uint32_t)((wm * 32 + mi * 16 + (l & 15)) * APITCH +
                               ks * 16 + (l >> 4) * 8) * 2;
                ldm_x4(ah[mi], sb + MG_AHI + off);
                ldm_x4(al[mi], sb + MG_ALO + off);
            }
            uint32_t bh[4][2], bl[4][2];
#pragma unroll
            for (int ni = 0; ni < 4; ni++) {
                uint32_t off =
                    (uint32_t)((wn * 32 + ni * 8 + (l & 7)) * APITCH +
                               ks * 16 + ((l >> 3) & 1) * 8) * 2;
                ldm_x2(bh[ni], sb + MG_BHI + off);
                ldm_x2(bl[ni], sb + MG_BLO + off);
            }
#pragma unroll
            for (int mi = 0; mi < 2; mi++)
#pragma unroll
                for (int ni = 0; ni < 4; ni++) {
                    mma16816(c[mi][ni], ah[mi], bh[ni]);
                    mma16816(c[mi][ni], al[mi], bh[ni]);
                    mma16816(c[mi][ni], ah[mi], bl[ni]);
                }
        }
        __syncthreads();
    }

#pragma unroll
    for (int mi = 0; mi < 2; mi++) {
#pragma unroll
        for (int ni = 0; ni < 4; ni++) {
#pragma unroll
            for (int j = 0; j < 4; j++) {
                int row = m0 + wm * 32 + mi * 16 + (l >> 2) + (j >> 1) * 8;
                int col = n0 + wn * 32 + ni * 8 + (l & 3) * 2 + (j & 1);
                if (col < Nout)
                    C[(size_t)row * Nout + col] = c[mi][ni][j] + bias[col];
            }
        }
    }
}

// ---------------- reset for the L2-exchange state (run before each lstm launch) ----
__global__ void lstm_reset() {
    int idx = blockIdx.x * blockDim.x + threadIdx.x;
    if (idx < 2 * 2 * 8 * 1024) g_hx[idx] = 0.0f;
    if (idx < 2 * 8 * 8) g_flag[idx] = 0;
}

// ---------------- BiLSTM layer v10: register-W matvec, broadcast h ----------------
// R12/R13 exchange protocol unchanged. Matvec restructured:
//  - 256 threads = 64 gate-pairs x 4 k-quarters; each thread: 2 gates x 4 batches x 64 k
//  - W held in REGISTERS (2x16 float4), zero SMEM W traffic, no WhhT staging
//  - h loads are warp-uniform -> SMEM broadcast (conflict-free, ~free)
//  - partials in red4[kq][gate] (float4 over batches), assembled by tid<128
#define OFF_HBUF 0                                // 2048 floats (2 par x 1024)
#define OFF_RED  2048                             // 4*132 float4 = 2112 floats
#define OFF_GSM  (OFF_RED + 2112)                 // 512 floats
#define OFF_CSM  (OFF_GSM + 512)                  // 128 floats
#define LSTM_SMEM_FLOATS (OFF_CSM + 128)          // 4800
#define LSTM_SMEM_BYTES  (LSTM_SMEM_FLOATS * 4)   // 19200

__global__ void __launch_bounds__(256, 1)
lstm_layer(const float* __restrict__ GxF, const float* __restrict__ GxB,
           const float* __restrict__ WhhF, const float* __restrict__ WhhB,
           const int* __restrict__ lengths, float* __restrict__ Hout) {
    extern __shared__ float sm[];
    float*  hbuf = sm + OFF_HBUF;
    float4* red4 = (float4*)(sm + OFF_RED);
    float*  gsm  = sm + OFF_GSM;
    float*  csm  = sm + OFF_CSM;

    int tid = threadIdx.x;
    int l   = tid & 31;
    int r   = blockIdx.x & 7;
    int cid = blockIdx.x >> 3;
    int dir = cid >> 3;
    int bg  = cid & 7;
    int batch0 = bg * 4;

    const float* Gx  = dir ? GxB : GxF;
    const float* Whh = dir ? WhhB : WhhF;

    float* hx_base  = g_hx;                       // [par][dir][bg][1024]
    int*   flg_base = g_flag + (dir * 8 + bg) * 8;

    // matvec thread mapping: gate pair + k-quarter
    int gp = tid & 63;
    int kq = tid >> 6;
    int g0 = gp << 1, g1 = g0 + 1;
    int grow0 = ((g0 >> 5) << 8) + (r << 5) + (g0 & 31);
    int grow1 = ((g1 >> 5) << 8) + (r << 5) + (g1 & 31);

    // W slice into registers: 2 gates x 64 k (this thread's quarter)
    float4 w0[16], w1[16];
    {
        const float4* p0 = (const float4*)(Whh + (size_t)grow0 * 256 + kq * 64);
        const float4* p1 = (const float4*)(Whh + (size_t)grow1 * 256 + kq * 64);
#pragma unroll
        for (int i = 0; i < 16; i++) { w0[i] = p0[i]; w1[i] = p1[i]; }
    }
    if (tid < 128) csm[tid] = 0.0f;
    __syncthreads();

    // assembly/prefetch gate for tid<128
    int growa = ((tid >> 5) << 8) + (r << 5) + (tid & 31);

    int b2 = tid >> 5, uu = tid & 31;        // producer mapping (tid<128)
    int mylen = 0;
    if (tid < 128) mylen = lengths[batch0 + b2];
    float hreg = 0.0f;

    for (int s = 0; s < TT; ++s) {
        int t = dir ? (TT - 1 - s) : s;
        int par = s & 1;

        // prefetch gate-x for this step before polling (tid<128, gate=tid, 4 batches)
        float gxa = 0.f, gxb2 = 0.f, gxc = 0.f, gxd = 0.f;
        if (tid < 128) {
            const float* gpx = Gx + ((size_t)t * BB + batch0) * GATES + growa;
            gxa = gpx[0]; gxb2 = gpx[GATES]; gxc = gpx[2 * GATES]; gxd = gpx[3 * GATES];
        }

        // wait for all 8 ranks' h slices: each rank adds 128 per step
        if (s > 0) {
            int need = 128 * s;
            for (;;) {
                bool ok = (l < 8) ? (ld_acq(flg_base + l) >= need) : true;
                if (__all_sync(0xffffffffu, ok)) break;
            }
        }

        // copy full h (1024 floats) L2 -> smem[par]
        {
            const float4* src = (const float4*)(hx_base + ((par * 2 + dir) * 8 + bg) * 1024);
            float4 v = __ldcg(src + tid);
            *(float4*)&hbuf[par * 1024 + tid * 4] = v;
        }
        __syncthreads();

        // matvec: 2 gates x 4 batches x 64 k, W in regs, h via SMEM broadcast
        const float* hb = hbuf + par * 1024 + kq * 64;
        float a0[4] = {0.f, 0.f, 0.f, 0.f};
        float a1[4] = {0.f, 0.f, 0.f, 0.f};
#pragma unroll
        for (int i = 0; i < 16; i++) {
#pragma unroll
            for (int b = 0; b < 4; b++) {
                float4 h4 = *(const float4*)(hb + b * 256 + i * 4);
                a0[b] += w0[i].x * h4.x + w0[i].y * h4.y + w0[i].z * h4.z + w0[i].w * h4.w;
                a1[b] += w1[i].x * h4.x + w1[i].y * h4.y + w1[i].z * h4.z + w1[i].w * h4.w;
            }
        }
        red4[kq * 132 + g0] = make_float4(a0[0], a0[1], a0[2], a0[3]);
        red4[kq * 132 + g1] = make_float4(a1[0], a1[1], a1[2], a1[3]);
        __syncthreads();

        // assemble gate pre-activations (tid<128, gate = tid) + scatter to gsm
        if (tid < 128) {
            float4 s0 = red4[0 * 132 + tid];
            float4 s1 = red4[1 * 132 + tid];
            float4 s2 = red4[2 * 132 + tid];
            float4 s3 = red4[3 * 132 + tid];
            float tb0 = s0.x + s1.x + s2.x + s3.x + gxa;
            float tb1 = s0.y + s1.y + s2.y + s3.y + gxb2;
            float tb2 = s0.z + s1.z + s2.z + s3.z + gxc;
            float tb3 = s0.w + s1.w + s2.w + s3.w + gxd;
            int q = tid >> 5, u = tid & 31;
            gsm[(0 * 4 + q) * 32 + u] = tb0;
            gsm[(1 * 4 + q) * 32 + u] = tb1;
            gsm[(2 * 4 + q) * 32 + u] = tb2;
            gsm[(3 * 4 + q) * 32 + u] = tb3;
        }
        __syncthreads();

        if (tid < 128) {
            float iv = gsm[(b2 * 4 + 0) * 32 + uu];
            float fv = gsm[(b2 * 4 + 1) * 32 + uu];
            float gv = gsm[(b2 * 4 + 2) * 32 + uu];
            float ov = gsm[(b2 * 4 + 3) * 32 + uu];
            float c  = csm[b2 * 32 + uu];
            float c2 = sigf(fv) * c + sigf(iv) * tanh_fast(gv);
            float h2 = sigf(ov) * tanh_fast(c2);
            bool m = (t < mylen);
            float hn = m ? h2 : hreg;
            float cn = m ? c2 : c;
            csm[b2 * 32 + uu] = cn;
            hreg = hn;

            if (s < TT - 1) {
                // publish own slice for step s+1, then release-increment the
                // flag counter (orders THIS thread's h store before the add)
                hx_base[(((par ^ 1) * 2 + dir) * 8 + bg) * 1024 +
                        (b2 << 8) + (r << 5) + uu] = hn;
                red_add_release(flg_base + r, 1);
            }
            // Hout (DRAM) AFTER signaling — off the critical path
            Hout[((size_t)t * BB + batch0 + b2) * 512 + dir * 256 + (r << 5) + uu] =
                m ? h2 : 0.0f;
        }
        // no trailing syncthreads: next iteration's post-copy sync covers
        // red4/gsm reuse (copy writes the opposite parity hbuf half)
    }
}

// ---------------- emit transpose + mask output ----------------
__global__ void finalize_kernel(const float* __restrict__ emitb,
                                const int* __restrict__ sent,
                                float* __restrict__ out, int out_size) {
    int bid = blockIdx.x;            // b*256 + t
    int b = bid >> 8, t = bid & 255;
    int k = threadIdx.x;
    if (k < KK) out[(size_t)bid * KK + k] = emitb[((size_t)t * BB + b) * KK + k];
    if (k == KK) {
        int idx = MASK_OFF + bid;
        if (idx < out_size) out[idx] = (sent[bid] != 0) ? 1.0f : 0.0f;
    }
}

// ---------------- CRF v2: 96 threads, 2 threads per tag, fast exp/log ----------------
__global__ void crf_kernel(const float* __restrict__ emitb,
                           const int* __restrict__ tags,
                           const int* __restrict__ lengths,
                           const float* __restrict__ start_t,
                           const float* __restrict__ end_t,
                           const float* __restrict__ trans,
                           float* __restrict__ scratch) {
    int b = blockIdx.x;
    int tid = threadIdx.x;           // 96
    __shared__ float trs[KK * KK];
    __shared__ float score[KK];
    __shared__ float rbuf[64];
    __shared__ float numsh;

    for (int i = tid; i < KK * KK; i += 96) trs[i] = trans[i];
    int len = lengths[b];
    __syncthreads();

    // numerator on threads 0..63 (deterministic fixed-tree reduction)
    if (tid < 64) {
        float part = 0.0f;
        for (int t = 1 + tid; t < len; t += 64) {
            int tg = tags[b * TT + t];
            int pg = tags[b * TT + t - 1];
            part += trs[pg * KK + tg] + emitb[((size_t)t * BB + b) * KK + tg];
        }
        rbuf[tid] = part;
    }
    __syncthreads();
    for (int s = 32; s > 0; s >>= 1) {
        if (tid < s) rbuf[tid] += rbuf[tid + s];
        __syncthreads();
    }
    if (tid == 0) {
        int t0 = tags[b * TT + 0];
        numsh = rbuf[0] + start_t[t0] + emitb[(size_t)b * KK + t0]
              + end_t[tags[b * TT + len - 1]];
    }

    // denominator: forward algorithm, 2 threads per k (j split 24/24)
    int k    = tid >> 1;             // 0..47
    int half = tid & 1;
    int jb   = half * 24;

    if (tid < KK) score[tid] = start_t[tid] + emitb[(size_t)b * KK + tid];
    __syncthreads();
    for (int t = 1; t < len; t++) {
        float m = -1e30f;
#pragma unroll 4
        for (int j = 0; j < 24; j++) {
            float v = score[jb + j] + trs[(jb + j) * KK + k];
            m = fmaxf(m, v);
        }
        float m2 = fmaxf(m, __shfl_xor_sync(0xffffffffu, m, 1));
        float ssum = 0.0f;
#pragma unroll 4
        for (int j = 0; j < 24; j++)
            ssum += __expf(score[jb + j] + trs[(jb + j) * KK + k] - m2);
        ssum += __shfl_xor_sync(0xffffffffu, ssum, 1);
        float nv = m2 + __logf(ssum) + emitb[((size_t)t * BB + b) * KK + k];
        __syncthreads();
        if (half == 0) score[k] = nv;
        __syncthreads();
    }
    if (tid == 0) {
        float m = -1e30f;
        for (int kk2 = 0; kk2 < KK; kk2++) m = fmaxf(m, score[kk2] + end_t[kk2]);
        float ssum = 0.0f;
        for (int kk2 = 0; kk2 < KK; kk2++) ssum += __expf(score[kk2] + end_t[kk2] - m);
        float den = m + __logf(ssum);
        scratch[b] = numsh - den;
    }
}

__global__ void loss_kernel(const float* __restrict__ scratch,
                            float* __restrict__ out, int out_size) {
    if (threadIdx.x == 0 && LOSS_OFF < out_size) {
        float s = 0.0f;
        for (int b = 0; b < BB; b++) s += scratch[b];
        out[LOSS_OFF] = s / (float)BB;
    }
}

// ---------------- launch ----------------
extern "C" void kernel_launch(void* const* d_in, const int* in_sizes, int n_in,
                              void* d_out, int out_size) {
    const int*   sentence = (const int*)d_in[0];
    const int*   lengths  = (const int*)d_in[1];
    const int*   tags     = (const int*)d_in[2];
    const float* embed    = (const float*)d_in[3];
    const float* Wih0f = (const float*)d_in[4];
    const float* Whh0f = (const float*)d_in[5];
    const float* b0f   = (const float*)d_in[6];
    const float* Wih0b = (const float*)d_in[7];
    const float* Whh0b = (const float*)d_in[8];
    const float* b0b   = (const float*)d_in[9];
    const float* Wih1f = (const float*)d_in[10];
    const float* Whh1f = (const float*)d_in[11];
    const float* b1f   = (const float*)d_in[12];
    const float* Wih1b = (const float*)d_in[13];
    const float* Whh1b = (const float*)d_in[14];
    const float* b1b   = (const float*)d_in[15];
    const float* Wout  = (const float*)d_in[16];
    const float* bout  = (const float*)d_in[17];
    const float* start_t = (const float*)d_in[18];
    const float* end_t   = (const float*)d_in[19];
    const float* trans   = (const float*)d_in[20];
    float* out = (float*)d_out;

    float *x0, *gxf, *gxb, *h1, *h2, *emitb, *scr;
    cudaGetSymbolAddress((void**)&x0, g_x0);
    cudaGetSymbolAddress((void**)&gxf, g_gxf);
    cudaGetSymbolAddress((void**)&gxb, g_gxb);
    cudaGetSymbolAddress((void**)&h1, g_h1);
    cudaGetSymbolAddress((void**)&h2, g_h2);
    cudaGetSymbolAddress((void**)&emitb, g_emit);
    cudaGetSymbolAddress((void**)&scr, g_scr);

    cudaFuncSetAttribute(lstm_layer, cudaFuncAttributeMaxDynamicSharedMemorySize,
                         LSTM_SMEM_BYTES);
    cudaFuncSetAttribute(mma_gemm, cudaFuncAttributeMaxDynamicSharedMemorySize,
                         MG_TOTAL);

    embed_kernel<<<ROWS_TB, 256>>>(sentence, embed, x0);

    // layer 0
    mma_gemm<<<dim3(16, 64, 2), 256, MG_TOTAL>>>(
        x0, Wih0f, Wih0b, b0f, b0b, gxf, gxb, 256, GATES);
    lstm_reset<<<128, 256>>>();
    lstm_layer<<<128, 256, LSTM_SMEM_BYTES>>>(gxf, gxb, Whh0f, Whh0b, lengths, h1);

    // layer 1
    mma_gemm<<<dim3(16, 64, 2), 256, MG_TOTAL>>>(
        h1, Wih1f, Wih1b, b1f, b1b, gxf, gxb, 512, GATES);
    lstm_reset<<<128, 256>>>();
    lstm_layer<<<128, 256, LSTM_SMEM_BYTES>>>(gxf, gxb, Whh1f, Whh1b, lengths, h2);

    // emissions
    mma_gemm<<<dim3(1, 64, 1), 256, MG_TOTAL>>>(
        h2, Wout, Wout, bout, bout, emitb, emitb, 512, KK);

    finalize_kernel<<<BB * TT, 64>>>(emitb, sentence, out, out_size);
    crf_kernel<<<BB, 96>>>(emitb, tags, lengths, start_t, end_t, trans, scr);
    loss_kernel<<<1, 32>>>(scr, out, out_size);
}

// round 16
// speedup vs baseline: 2.4956x; 1.0684x over previous
#include <cuda_runtime.h>
#include <cuda_bf16.h>
#include <cstdint>
#include <math.h>

#define TT 256
#define BB 32
#define HH 256
#define KK 48
#define GATES 1024          // 4*H
#define ROWS_TB (TT*BB)     // 8192

// ---------------- device scratch (no allocations allowed) ----------------
__device__ float g_x0[ROWS_TB * 256];        // embedded input (t,b,e)
__device__ float g_gxf[ROWS_TB * GATES];     // x@Wih^T + b, fwd
__device__ float g_gxb[ROWS_TB * GATES];     // x@Wih^T + b, bwd
__device__ float g_h1[ROWS_TB * 512];        // layer-0 output (hf|hb)
__device__ float g_h2[ROWS_TB * 512];        // layer-1 output
__device__ float g_emit[ROWS_TB * KK];       // emissions (t,b,k)
__device__ float g_scr[BB];                  // per-batch (num-den)

// L2-exchange: h[par][dir][bg][b*256+u], flags [dir][bg][rank] (counters, +128/step)
__device__ float g_hx[2 * 2 * 8 * 1024];     // 128 KB
__device__ int   g_flag[2 * 8 * 8];          // 128 ints

// output layout: [emit (B,T,K) fp32 | loss | mask (B,T)]
#define EMIT_N   (BB*TT*KK)      // 393216
#define LOSS_OFF EMIT_N
#define MASK_OFF (EMIT_N + 1)

// ---------------- helpers ----------------
__device__ __forceinline__ float sigf(float x) { return 1.0f / (1.0f + __expf(-x)); }
__device__ __forceinline__ float tanh_fast(float x) {
    return 2.0f / (1.0f + __expf(-2.0f * x)) - 1.0f;
}

__device__ __forceinline__ uint32_t smem_u32(const void* p) {
    uint32_t a;
    asm("{ .reg .u64 t; cvta.to.shared.u64 t, %1; cvt.u32.u64 %0, t; }" : "=r"(a) : "l"(p));
    return a;
}
// pack (lo half = a, hi half = b) into bf16x2
__device__ __forceinline__ uint32_t pk2(float a, float b) {
    uint32_t r;
    asm("cvt.rn.bf16x2.f32 %0, %1, %2;" : "=r"(r) : "f"(b), "f"(a));
    return r;
}
// packed fp32x2 helpers (sm_100+ dual-FMA path)
__device__ __forceinline__ unsigned long long pk64(float lo, float hi) {
    unsigned long long v;
    asm("mov.b64 %0, {%1, %2};" : "=l"(v) : "f"(lo), "f"(hi));
    return v;
}
__device__ __forceinline__ void fma2(unsigned long long& acc, unsigned long long a,
                                     unsigned long long b) {
    asm("fma.rn.f32x2 %0, %1, %2, %0;" : "+l"(acc) : "l"(a), "l"(b));
}
__device__ __forceinline__ float hsum2(unsigned long long v) {
    float lo, hi;
    asm("mov.b64 {%0, %1}, %2;" : "=f"(lo), "=f"(hi) : "l"(v));
    return lo + hi;
}
__device__ __forceinline__ void ldm_x4(uint32_t* r, uint32_t addr) {
    asm volatile("ldmatrix.sync.aligned.m8n8.x4.shared.b16 {%0,%1,%2,%3}, [%4];"
                 : "=r"(r[0]), "=r"(r[1]), "=r"(r[2]), "=r"(r[3]) : "r"(addr));
}
__device__ __forceinline__ void ldm_x2(uint32_t* r, uint32_t addr) {
    asm volatile("ldmatrix.sync.aligned.m8n8.x2.shared.b16 {%0,%1}, [%2];"
                 : "=r"(r[0]), "=r"(r[1]) : "r"(addr));
}
__device__ __forceinline__ void mma16816(float* c, const uint32_t* a, const uint32_t* b) {
    asm volatile("mma.sync.aligned.m16n8k16.row.col.f32.bf16.bf16.f32 "
                 "{%0,%1,%2,%3}, {%4,%5,%6,%7}, {%8,%9}, {%0,%1,%2,%3};"
                 : "+f"(c[0]), "+f"(c[1]), "+f"(c[2]), "+f"(c[3])
                 : "r"(a[0]), "r"(a[1]), "r"(a[2]), "r"(a[3]), "r"(b[0]), "r"(b[1]));
}
__device__ __forceinline__ int ld_acq(const int* p) {
    int v;
    asm volatile("ld.acquire.gpu.global.s32 %0, [%1];" : "=r"(v) : "l"(p) : "memory");
    return v;
}
// per-producer release-increment on the step counter: orders this thread's
// prior global stores (the h publish) before the increment, no block fence.
__device__ __forceinline__ void red_add_release(int* p, int v) {
    asm volatile("red.release.gpu.global.add.s32 [%0], %1;" :: "l"(p), "r"(v) : "memory");
}

// ---------------- embedding gather ----------------
__global__ void embed_kernel(const int* __restrict__ sent,
                             const float* __restrict__ embed,
                             float* __restrict__ x0) {
    int bid = blockIdx.x;            // t*32 + b
    int t = bid >> 5, b = bid & 31;
    int tok = sent[b * TT + t];
    x0[(size_t)bid * 256 + threadIdx.x] = embed[(size_t)tok * 256 + threadIdx.x];
}

// ---------------- mma.sync bf16x3 GEMM: C[M,N] = A[M,K] * W[N,K]^T + bias ----------------
#define MG_AHI 0
#define MG_ALO 18432
#define MG_BHI 36864
#define MG_BLO 46080
#define MG_TOTAL 55296
#define APITCH 72

__global__ void __launch_bounds__(256)
mma_gemm(const float* __restrict__ A,
         const float* __restrict__ Wf, const float* __restrict__ Wb,
         const float* __restrict__ biasf, const float* __restrict__ biasb,
         float* __restrict__ Cf, float* __restrict__ Cb,
         int K, int Nout) {
    extern __shared__ char smc[];
    uint32_t sb = smem_u32(smc);
    int tid = threadIdx.x, wid = tid >> 5, l = tid & 31;
    int m0 = blockIdx.y * 128, n0 = blockIdx.x * 64;
    const float* W    = blockIdx.z ? Wb : Wf;
    const float* bias = blockIdx.z ? biasb : biasf;
    float*       C    = blockIdx.z ? Cb : Cf;

    int wm = wid & 3, wn = wid >> 2;
    int srow = tid >> 4;
    int scol = (tid & 15) << 2;

    float c[2][4][4];
#pragma unroll
    for (int mi = 0; mi < 2; mi++)
#pragma unroll
        for (int ni = 0; ni < 4; ni++)
#pragma unroll
            for (int j = 0; j < 4; j++) c[mi][ni][j] = 0.0f;

    int nch = K >> 6;
    for (int ch = 0; ch < nch; ch++) {
        int kc = ch << 6;
#pragma unroll
        for (int rr = 0; rr < 8; rr++) {
            int row = srow + rr * 16;
            float4 v = *(const float4*)&A[(size_t)(m0 + row) * K + kc + scol];
            float hx = __bfloat162float(__float2bfloat16(v.x));
            float hy = __bfloat162float(__float2bfloat16(v.y));
            float hz = __bfloat162float(__float2bfloat16(v.z));
            float hw = __bfloat162float(__float2bfloat16(v.w));
            uint32_t off = (uint32_t)(row * APITCH + scol) * 2;
            *(uint2*)(smc + MG_AHI + off) = make_uint2(pk2(hx, hy), pk2(hz, hw));
            *(uint2*)(smc + MG_ALO + off) =
                make_uint2(pk2(v.x - hx, v.y - hy), pk2(v.z - hz, v.w - hw));
        }
#pragma unroll
        for (int rr = 0; rr < 4; rr++) {
            int row = srow + rr * 16;
            int n = n0 + row;
            float4 v = make_float4(0.f, 0.f, 0.f, 0.f);
            if (n < Nout) v = *(const float4*)&W[(size_t)n * K + kc + scol];
            float hx = __bfloat162float(__float2bfloat16(v.x));
            float hy = __bfloat162float(__float2bfloat16(v.y));
            float hz = __bfloat162float(__float2bfloat16(v.z));
            float hw = __bfloat162float(__float2bfloat16(v.w));
            uint32_t off = (uint32_t)(row * APITCH + scol) * 2;
            *(uint2*)(smc + MG_BHI + off) = make_uint2(pk2(hx, hy), pk2(hz, hw));
            *(uint2*)(smc + MG_BLO + off) =
                make_uint2(pk2(v.x - hx, v.y - hy), pk2(v.z - hz, v.w - hw));
        }
        __syncthreads();

#pragma unroll
        for (int ks = 0; ks < 4; ks++) {
            uint32_t ah[2][4], al[2][4];
#pragma unroll
            for (int mi = 0; mi < 2; mi++) {
                uint32_t off =
                    (uint32_t)((wm * 32 + mi * 16 + (l & 15)) * APITCH +
                               ks * 16 + (l >> 4) * 8) * 2;
                ldm_x4(ah[mi], sb + MG_AHI + off);
                ldm_x4(al[mi], sb + MG_ALO + off);
            }
            uint32_t bh[4][2], bl[4][2];
#pragma unroll
            for (int ni = 0; ni < 4; ni++) {
                uint32_t off =
                    (uint32_t)((wn * 32 + ni * 8 + (l & 7)) * APITCH +
                               ks * 16 + ((l >> 3) & 1) * 8) * 2;
                ldm_x2(bh[ni], sb + MG_BHI + off);
                ldm_x2(bl[ni], sb + MG_BLO + off);
            }
#pragma unroll
            for (int mi = 0; mi < 2; mi++)
#pragma unroll
                for (int ni = 0; ni < 4; ni++) {
                    mma16816(c[mi][ni], ah[mi], bh[ni]);
                    mma16816(c[mi][ni], al[mi], bh[ni]);
                    mma16816(c[mi][ni], ah[mi], bl[ni]);
                }
        }
        __syncthreads();
    }

#pragma unroll
    for (int mi = 0; mi < 2; mi++) {
#pragma unroll
        for (int ni = 0; ni < 4; ni++) {
#pragma unroll
            for (int j = 0; j < 4; j++) {
                int row = m0 + wm * 32 + mi * 16 + (l >> 2) + (j >> 1) * 8;
                int col = n0 + wn * 32 + ni * 8 + (l & 3) * 2 + (j & 1);
                if (col < Nout)
                    C[(size_t)row * Nout + col] = c[mi][ni][j] + bias[col];
            }
        }
    }
}

// ---------------- reset for the L2-exchange state (run before each lstm launch) ----
__global__ void lstm_reset() {
    int idx = blockIdx.x * blockDim.x + threadIdx.x;
    if (idx < 2 * 2 * 8 * 1024) g_hx[idx] = 0.0f;
    if (idx < 2 * 8 * 8) g_flag[idx] = 0;
}

// ---------------- BiLSTM layer v11: FFMA2 matvec + fused assemble/tail ----------------
// R15 structure, two changes:
//  - matvec uses fma.rn.f32x2 (paired over adjacent k): W pre-packed into b64
//    register pairs at init; h float4 reinterpreted as 2x b64 (no pack in loop).
//    FFMA issue floor ~2048 -> ~1100 cy.
//  - partials stored batch-major red[b][kq][g] (scalar): tail reads conflict-free
//    and fuses assemble+gates, removing the gsm stage and one __syncthreads.
#define OFF_HBUF 0                                // 2048 floats (2 par x 1024)
#define OFF_RED  2048                             // 4*528 floats = 2112
#define OFF_CSM  (OFF_RED + 2112)                 // 128 floats
#define LSTM_SMEM_FLOATS (OFF_CSM + 128)          // 4288
#define LSTM_SMEM_BYTES  (LSTM_SMEM_FLOATS * 4)   // 17152

__global__ void __launch_bounds__(256, 1)
lstm_layer(const float* __restrict__ GxF, const float* __restrict__ GxB,
           const float* __restrict__ WhhF, const float* __restrict__ WhhB,
           const int* __restrict__ lengths, float* __restrict__ Hout) {
    extern __shared__ float sm[];
    float* hbuf = sm + OFF_HBUF;
    float* red  = sm + OFF_RED;
    float* csm  = sm + OFF_CSM;

    int tid = threadIdx.x;
    int l   = tid & 31;
    int r   = blockIdx.x & 7;
    int cid = blockIdx.x >> 3;
    int dir = cid >> 3;
    int bg  = cid & 7;
    int batch0 = bg * 4;

    const float* Gx  = dir ? GxB : GxF;
    const float* Whh = dir ? WhhB : WhhF;

    float* hx_base  = g_hx;                       // [par][dir][bg][1024]
    int*   flg_base = g_flag + (dir * 8 + bg) * 8;

    // matvec thread mapping: gate pair + k-quarter
    int gp = tid & 63;
    int kq = tid >> 6;
    int g0 = gp << 1, g1 = g0 + 1;
    int grow0 = ((g0 >> 5) << 8) + (r << 5) + (g0 & 31);
    int grow1 = ((g1 >> 5) << 8) + (r << 5) + (g1 & 31);

    // W slice into b64 register pairs: 2 gates x 64 k (32 pairs each)
    unsigned long long w0p[32], w1p[32];
    {
        const float4* p0 = (const float4*)(Whh + (size_t)grow0 * 256 + kq * 64);
        const float4* p1 = (const float4*)(Whh + (size_t)grow1 * 256 + kq * 64);
#pragma unroll
        for (int i = 0; i < 16; i++) {
            float4 a = p0[i], b = p1[i];
            w0p[2 * i]     = pk64(a.x, a.y);
            w0p[2 * i + 1] = pk64(a.z, a.w);
            w1p[2 * i]     = pk64(b.x, b.y);
            w1p[2 * i + 1] = pk64(b.z, b.w);
        }
    }
    if (tid < 128) csm[tid] = 0.0f;
    __syncthreads();

    int b2 = tid >> 5, uu = tid & 31;        // producer/tail mapping (tid<128)
    int mylen = 0;
    if (tid < 128) mylen = lengths[batch0 + b2];
    float hreg = 0.0f;

    for (int s = 0; s < TT; ++s) {
        int t = dir ? (TT - 1 - s) : s;
        int par = s & 1;

        // prefetch gate-x for this step before polling (tid<128: batch b2, unit uu)
        float gxi = 0.f, gxfv = 0.f, gxg = 0.f, gxo = 0.f;
        if (tid < 128) {
            const float* gpx = Gx + ((size_t)t * BB + batch0 + b2) * GATES + (r << 5) + uu;
            gxi = gpx[0]; gxfv = gpx[256]; gxg = gpx[512]; gxo = gpx[768];
        }

        // wait for all 8 ranks' h slices: each rank adds 128 per step
        if (s > 0) {
            int need = 128 * s;
            for (;;) {
                bool ok = (l < 8) ? (ld_acq(flg_base + l) >= need) : true;
                if (__all_sync(0xffffffffu, ok)) break;
            }
        }

        // copy full h (1024 floats) L2 -> smem[par]
        {
            const float4* src = (const float4*)(hx_base + ((par * 2 + dir) * 8 + bg) * 1024);
            float4 v = __ldcg(src + tid);
            *(float4*)&hbuf[par * 1024 + tid * 4] = v;
        }
        __syncthreads();

        // matvec (FFMA2): 2 gates x 4 batches x 64 k; W in b64 reg pairs,
        // h via SMEM broadcast reinterpreted as b64 pairs
        const float* hb = hbuf + par * 1024 + kq * 64;
        unsigned long long ac0[4] = {0ull, 0ull, 0ull, 0ull};
        unsigned long long ac1[4] = {0ull, 0ull, 0ull, 0ull};
#pragma unroll
        for (int i = 0; i < 16; i++) {
#pragma unroll
            for (int b = 0; b < 4; b++) {
                ulonglong2 hp = *(const ulonglong2*)(hb + b * 256 + i * 4);
                fma2(ac0[b], w0p[2 * i],     hp.x);
                fma2(ac0[b], w0p[2 * i + 1], hp.y);
                fma2(ac1[b], w1p[2 * i],     hp.x);
                fma2(ac1[b], w1p[2 * i + 1], hp.y);
            }
        }
        // partials batch-major: red[b*528 + kq*132 + g]
#pragma unroll
        for (int b = 0; b < 4; b++) {
            red[b * 528 + kq * 132 + g0] = hsum2(ac0[b]);
            red[b * 528 + kq * 132 + g1] = hsum2(ac1[b]);
        }
        __syncthreads();

        // fused assemble + gates + publish (tid<128: batch b2, unit uu)
        if (tid < 128) {
            const float* rb = red + b2 * 528;
            float iv = rb[0 * 132 + uu]       + rb[1 * 132 + uu]
                     + rb[2 * 132 + uu]       + rb[3 * 132 + uu]       + gxi;
            float fv = rb[0 * 132 + 32 + uu]  + rb[1 * 132 + 32 + uu]
                     + rb[2 * 132 + 32 + uu]  + rb[3 * 132 + 32 + uu]  + gxfv;
            float gv = rb[0 * 132 + 64 + uu]  + rb[1 * 132 + 64 + uu]
                     + rb[2 * 132 + 64 + uu]  + rb[3 * 132 + 64 + uu]  + gxg;
            float ov = rb[0 * 132 + 96 + uu]  + rb[1 * 132 + 96 + uu]
                     + rb[2 * 132 + 96 + uu]  + rb[3 * 132 + 96 + uu]  + gxo;
            float c  = csm[b2 * 32 + uu];
            float c2 = sigf(fv) * c + sigf(iv) * tanh_fast(gv);
            float h2 = sigf(ov) * tanh_fast(c2);
            bool m = (t < mylen);
            float hn = m ? h2 : hreg;
            float cn = m ? c2 : c;
            csm[b2 * 32 + uu] = cn;
            hreg = hn;

            if (s < TT - 1) {
                // publish own slice for step s+1, then release-increment the
                // flag counter (orders THIS thread's h store before the add)
                hx_base[(((par ^ 1) * 2 + dir) * 8 + bg) * 1024 +
                        (b2 << 8) + (r << 5) + uu] = hn;
                red_add_release(flg_base + r, 1);
            }
            // Hout (DRAM) AFTER signaling — off the critical path
            Hout[((size_t)t * BB + batch0 + b2) * 512 + dir * 256 + (r << 5) + uu] =
                m ? h2 : 0.0f;
        }
        // no trailing syncthreads: next iteration's post-copy sync covers
        // red/hbuf reuse (copy writes the opposite parity hbuf half)
    }
}

// ---------------- emit transpose + mask output ----------------
__global__ void finalize_kernel(const float* __restrict__ emitb,
                                const int* __restrict__ sent,
                                float* __restrict__ out, int out_size) {
    int bid = blockIdx.x;            // b*256 + t
    int b = bid >> 8, t = bid & 255;
    int k = threadIdx.x;
    if (k < KK) out[(size_t)bid * KK + k] = emitb[((size_t)t * BB + b) * KK + k];
    if (k == KK) {
        int idx = MASK_OFF + bid;
        if (idx < out_size) out[idx] = (sent[bid] != 0) ? 1.0f : 0.0f;
    }
}

// ---------------- CRF v2: 96 threads, 2 threads per tag, fast exp/log ----------------
__global__ void crf_kernel(const float* __restrict__ emitb,
                           const int* __restrict__ tags,
                           const int* __restrict__ lengths,
                           const float* __restrict__ start_t,
                           const float* __restrict__ end_t,
                           const float* __restrict__ trans,
                           float* __restrict__ scratch) {
    int b = blockIdx.x;
    int tid = threadIdx.x;           // 96
    __shared__ float trs[KK * KK];
    __shared__ float score[KK];
    __shared__ float rbuf[64];
    __shared__ float numsh;

    for (int i = tid; i < KK * KK; i += 96) trs[i] = trans[i];
    int len = lengths[b];
    __syncthreads();

    // numerator on threads 0..63 (deterministic fixed-tree reduction)
    if (tid < 64) {
        float part = 0.0f;
        for (int t = 1 + tid; t < len; t += 64) {
            int tg = tags[b * TT + t];
            int pg = tags[b * TT + t - 1];
            part += trs[pg * KK + tg] + emitb[((size_t)t * BB + b) * KK + tg];
        }
        rbuf[tid] = part;
    }
    __syncthreads();
    for (int s = 32; s > 0; s >>= 1) {
        if (tid < s) rbuf[tid] += rbuf[tid + s];
        __syncthreads();
    }
    if (tid == 0) {
        int t0 = tags[b * TT + 0];
        numsh = rbuf[0] + start_t[t0] + emitb[(size_t)b * KK + t0]
              + end_t[tags[b * TT + len - 1]];
    }

    // denominator: forward algorithm, 2 threads per k (j split 24/24)
    int k    = tid >> 1;             // 0..47
    int half = tid & 1;
    int jb   = half * 24;

    if (tid < KK) score[tid] = start_t[tid] + emitb[(size_t)b * KK + tid];
    __syncthreads();
    for (int t = 1; t < len; t++) {
        float m = -1e30f;
#pragma unroll 4
        for (int j = 0; j < 24; j++) {
            float v = score[jb + j] + trs[(jb + j) * KK + k];
            m = fmaxf(m, v);
        }
        float m2 = fmaxf(m, __shfl_xor_sync(0xffffffffu, m, 1));
        float ssum = 0.0f;
#pragma unroll 4
        for (int j = 0; j < 24; j++)
            ssum += __expf(score[jb + j] + trs[(jb + j) * KK + k] - m2);
        ssum += __shfl_xor_sync(0xffffffffu, ssum, 1);
        float nv = m2 + __logf(ssum) + emitb[((size_t)t * BB + b) * KK + k];
        __syncthreads();
        if (half == 0) score[k] = nv;
        __syncthreads();
    }
    if (tid == 0) {
        float m = -1e30f;
        for (int kk2 = 0; kk2 < KK; kk2++) m = fmaxf(m, score[kk2] + end_t[kk2]);
        float ssum = 0.0f;
        for (int kk2 = 0; kk2 < KK; kk2++) ssum += __expf(score[kk2] + end_t[kk2] - m);
        float den = m + __logf(ssum);
        scratch[b] = numsh - den;
    }
}

__global__ void loss_kernel(const float* __restrict__ scratch,
                            float* __restrict__ out, int out_size) {
    if (threadIdx.x == 0 && LOSS_OFF < out_size) {
        float s = 0.0f;
        for (int b = 0; b < BB; b++) s += scratch[b];
        out[LOSS_OFF] = s / (float)BB;
    }
}

// ---------------- launch ----------------
extern "C" void kernel_launch(void* const* d_in, const int* in_sizes, int n_in,
                              void* d_out, int out_size) {
    const int*   sentence = (const int*)d_in[0];
    const int*   lengths  = (const int*)d_in[1];
    const int*   tags     = (const int*)d_in[2];
    const float* embed    = (const float*)d_in[3];
    const float* Wih0f = (const float*)d_in[4];
    const float* Whh0f = (const float*)d_in[5];
    const float* b0f   = (const float*)d_in[6];
    const float* Wih0b = (const float*)d_in[7];
    const float* Whh0b = (const float*)d_in[8];
    const float* b0b   = (const float*)d_in[9];
    const float* Wih1f = (const float*)d_in[10];
    const float* Whh1f = (const float*)d_in[11];
    const float* b1f   = (const float*)d_in[12];
    const float* Wih1b = (const float*)d_in[13];
    const float* Whh1b = (const float*)d_in[14];
    const float* b1b   = (const float*)d_in[15];
    const float* Wout  = (const float*)d_in[16];
    const float* bout  = (const float*)d_in[17];
    const float* start_t = (const float*)d_in[18];
    const float* end_t   = (const float*)d_in[19];
    const float* trans   = (const float*)d_in[20];
    float* out = (float*)d_out;

    float *x0, *gxf, *gxb, *h1, *h2, *emitb, *scr;
    cudaGetSymbolAddress((void**)&x0, g_x0);
    cudaGetSymbolAddress((void**)&gxf, g_gxf);
    cudaGetSymbolAddress((void**)&gxb, g_gxb);
    cudaGetSymbolAddress((void**)&h1, g_h1);
    cudaGetSymbolAddress((void**)&h2, g_h2);
    cudaGetSymbolAddress((void**)&emitb, g_emit);
    cudaGetSymbolAddress((void**)&scr, g_scr);

    cudaFuncSetAttribute(lstm_layer, cudaFuncAttributeMaxDynamicSharedMemorySize,
                         LSTM_SMEM_BYTES);
    cudaFuncSetAttribute(mma_gemm, cudaFuncAttributeMaxDynamicSharedMemorySize,
                         MG_TOTAL);

    embed_kernel<<<ROWS_TB, 256>>>(sentence, embed, x0);

    // layer 0
    mma_gemm<<<dim3(16, 64, 2), 256, MG_TOTAL>>>(
        x0, Wih0f, Wih0b, b0f, b0b, gxf, gxb, 256, GATES);
    lstm_reset<<<128, 256>>>();
    lstm_layer<<<128, 256, LSTM_SMEM_BYTES>>>(gxf, gxb, Whh0f, Whh0b, lengths, h1);

    // layer 1
    mma_gemm<<<dim3(16, 64, 2), 256, MG_TOTAL>>>(
        h1, Wih1f, Wih1b, b1f, b1b, gxf, gxb, 512, GATES);
    lstm_reset<<<128, 256>>>();
    lstm_layer<<<128, 256, LSTM_SMEM_BYTES>>>(gxf, gxb, Whh1f, Whh1b, lengths, h2);

    // emissions
    mma_gemm<<<dim3(1, 64, 1), 256, MG_TOTAL>>>(
        h2, Wout, Wout, bout, bout, emitb, emitb, 512, KK);

    finalize_kernel<<<BB * TT, 64>>>(emitb, sentence, out, out_size);
    crf_kernel<<<BB, 96>>>(emitb, tags, lengths, start_t, end_t, trans, scr);
    loss_kernel<<<1, 32>>>(scr, out, out_size);
}